// round 1
// baseline (speedup 1.0000x reference)
#include <cuda_runtime.h>
#include <cuda_bf16.h>
#include <math.h>

// Problem constants
#define VOCAB 32000
#define EDIM  1024
#define MDIM  4096
#define NLAY  4
#define BATCH 4
#define SEQ   2048
#define NROWS (BATCH*SEQ)   // 8192

// ---------------------------------------------------------------------------
// Static device scratch (no allocations allowed)
// ---------------------------------------------------------------------------
__device__ float g_h   [NROWS * EDIM];          // 32 MB  embedding / ping
__device__ float g_q   [NROWS * EDIM];          // 32 MB
__device__ float g_k   [NROWS * EDIM];          // 32 MB
__device__ float g_v   [NROWS * EDIM];          // 32 MB
__device__ float g_sc  [(size_t)BATCH*SEQ*SEQ]; // 64 MB  scores / softmax weights
__device__ float g_mlp [NROWS * MDIM];          // 128 MB mlp hidden
__device__ float g_h2  [NROWS * EDIM];          // 32 MB  pong

// ---------------------------------------------------------------------------
// Embedding gather: h[r,:] = emb[x[r],:]
// ---------------------------------------------------------------------------
__global__ void embed_kernel(const int* __restrict__ x,
                             const float* __restrict__ emb,
                             float* __restrict__ h)
{
    int r = blockIdx.x;                 // 0..8191
    int row = x[r];
    const float4* src = (const float4*)(emb + (size_t)row * EDIM);
    float4* dst = (float4*)(h + (size_t)r * EDIM);
    dst[threadIdx.x] = src[threadIdx.x];   // 256 threads * 4 floats = 1024
}

// ---------------------------------------------------------------------------
// Generic batched SGEMM (row-major):  C = act( scale * A@B + bias )
//   A [N,K], B [K,Mo], C [N,Mo].  Block tile 128x128x8, 256 threads, 8x8/thread
// ---------------------------------------------------------------------------
#define BM 128
#define BN 128
#define BK 8

__global__ __launch_bounds__(256)
void gemm_nn(const float* __restrict__ A, const float* __restrict__ B,
             const float* __restrict__ bias, float* __restrict__ C,
             int N, int K, int Mo,
             size_t sA, size_t sB, size_t sC,
             int relu, float scale)
{
    A += (size_t)blockIdx.z * sA;
    B += (size_t)blockIdx.z * sB;
    C += (size_t)blockIdx.z * sC;

    __shared__ float As[BK][BM];
    __shared__ float Bs[BK][BN];

    const int tid  = threadIdx.x;
    const int row0 = blockIdx.y * BM;
    const int col0 = blockIdx.x * BN;
    const int tm   = (tid / 16) * 8;
    const int tn   = (tid % 16) * 8;

    // global load mapping
    const int am = tid >> 1;            // 0..127
    const int ak = (tid & 1) * 4;       // 0 or 4
    const int bk = tid >> 5;            // 0..7
    const int bn = (tid & 31) * 4;      // 0..124

    const float* Aptr = A + (size_t)(row0 + am) * K + ak;
    const float* Bptr = B + (size_t)bk * Mo + col0 + bn;

    float acc[8][8];
    #pragma unroll
    for (int i = 0; i < 8; i++)
        #pragma unroll
        for (int j = 0; j < 8; j++) acc[i][j] = 0.f;

    for (int k0 = 0; k0 < K; k0 += BK) {
        float4 av = *(const float4*)(Aptr + k0);
        As[ak+0][am] = av.x; As[ak+1][am] = av.y;
        As[ak+2][am] = av.z; As[ak+3][am] = av.w;
        *(float4*)&Bs[bk][bn] = *(const float4*)(Bptr + (size_t)k0 * Mo);
        __syncthreads();

        #pragma unroll
        for (int kk = 0; kk < BK; kk++) {
            float a[8], b[8];
            *(float4*)(a  ) = *(const float4*)&As[kk][tm];
            *(float4*)(a+4) = *(const float4*)&As[kk][tm+4];
            *(float4*)(b  ) = *(const float4*)&Bs[kk][tn];
            *(float4*)(b+4) = *(const float4*)&Bs[kk][tn+4];
            #pragma unroll
            for (int i = 0; i < 8; i++)
                #pragma unroll
                for (int j = 0; j < 8; j++)
                    acc[i][j] += a[i] * b[j];
        }
        __syncthreads();
    }

    #pragma unroll
    for (int i = 0; i < 8; i++) {
        float* crow = C + (size_t)(row0 + tm + i) * Mo + col0 + tn;
        #pragma unroll
        for (int j = 0; j < 8; j++) {
            float vv = acc[i][j] * scale;
            if (bias) vv += bias[col0 + tn + j];
            if (relu) vv = fmaxf(vv, 0.f);
            crow[j] = vv;
        }
    }
}

// ---------------------------------------------------------------------------
// NT SGEMM for scores:  C[s,t] = scale * sum_e A[s,e] * Bt[t,e]
// Skips blocks fully below the kept region (mask keeps t >= s).
// ---------------------------------------------------------------------------
__global__ __launch_bounds__(256)
void gemm_nt(const float* __restrict__ A, const float* __restrict__ Bt,
             float* __restrict__ C,
             int N, int K, int Mo,
             size_t sA, size_t sB, size_t sC,
             float scale)
{
    const int row0 = blockIdx.y * BM;
    const int col0 = blockIdx.x * BN;
    // entire block masked (all t < s) -> skip; softmax never reads it
    if (col0 + BN <= row0) return;

    A  += (size_t)blockIdx.z * sA;
    Bt += (size_t)blockIdx.z * sB;
    C  += (size_t)blockIdx.z * sC;

    __shared__ float As[BK][BM];
    __shared__ float Bs[BK][BN];

    const int tid = threadIdx.x;
    const int tm  = (tid / 16) * 8;
    const int tn  = (tid % 16) * 8;

    const int am = tid >> 1;
    const int ak = (tid & 1) * 4;

    const float* Aptr = A  + (size_t)(row0 + am) * K + ak;
    const float* Bptr = Bt + (size_t)(col0 + am) * K + ak;  // same mapping, transposed operand

    float acc[8][8];
    #pragma unroll
    for (int i = 0; i < 8; i++)
        #pragma unroll
        for (int j = 0; j < 8; j++) acc[i][j] = 0.f;

    for (int k0 = 0; k0 < K; k0 += BK) {
        float4 av = *(const float4*)(Aptr + k0);
        As[ak+0][am] = av.x; As[ak+1][am] = av.y;
        As[ak+2][am] = av.z; As[ak+3][am] = av.w;
        float4 bv = *(const float4*)(Bptr + k0);
        Bs[ak+0][am] = bv.x; Bs[ak+1][am] = bv.y;
        Bs[ak+2][am] = bv.z; Bs[ak+3][am] = bv.w;
        __syncthreads();

        #pragma unroll
        for (int kk = 0; kk < BK; kk++) {
            float a[8], b[8];
            *(float4*)(a  ) = *(const float4*)&As[kk][tm];
            *(float4*)(a+4) = *(const float4*)&As[kk][tm+4];
            *(float4*)(b  ) = *(const float4*)&Bs[kk][tn];
            *(float4*)(b+4) = *(const float4*)&Bs[kk][tn+4];
            #pragma unroll
            for (int i = 0; i < 8; i++)
                #pragma unroll
                for (int j = 0; j < 8; j++)
                    acc[i][j] += a[i] * b[j];
        }
        __syncthreads();
    }

    #pragma unroll
    for (int i = 0; i < 8; i++) {
        float* crow = C + (size_t)(row0 + tm + i) * Mo + col0 + tn;
        #pragma unroll
        for (int j = 0; j < 8; j++)
            crow[j] = acc[i][j] * scale;
    }
}

// ---------------------------------------------------------------------------
// Row softmax with anti-causal mask (keep t >= s); writes 0 for t < s.
// One block per (s,b) row.
// ---------------------------------------------------------------------------
__global__ __launch_bounds__(256)
void softmax_kernel(float* __restrict__ scores)
{
    const int s = blockIdx.x;
    const int b = blockIdx.y;
    float* row = scores + ((size_t)b * SEQ + s) * (size_t)SEQ;
    const int tid = threadIdx.x;
    __shared__ float red[256];

    float m = -1e30f;
    for (int t = s + tid; t < SEQ; t += 256) m = fmaxf(m, row[t]);
    red[tid] = m; __syncthreads();
    #pragma unroll
    for (int o = 128; o > 0; o >>= 1) {
        if (tid < o) red[tid] = fmaxf(red[tid], red[tid + o]);
        __syncthreads();
    }
    m = red[0];
    __syncthreads();

    float sum = 0.f;
    for (int t = s + tid; t < SEQ; t += 256) sum += expf(row[t] - m);
    red[tid] = sum; __syncthreads();
    #pragma unroll
    for (int o = 128; o > 0; o >>= 1) {
        if (tid < o) red[tid] += red[tid + o];
        __syncthreads();
    }
    const float inv = 1.f / red[0];

    for (int t = tid; t < SEQ; t += 256)
        row[t] = (t < s) ? 0.f : expf(row[t] - m) * inv;
}

// ---------------------------------------------------------------------------
// Host launch
// ---------------------------------------------------------------------------
static float* symaddr(const void* sym)
{
    void* p = nullptr;
    cudaGetSymbolAddress(&p, sym);
    return (float*)p;
}

extern "C" void kernel_launch(void* const* d_in, const int* in_sizes, int n_in,
                              void* d_out, int out_size)
{
    const int*   x   = (const int*)  d_in[0];
    const float* emb = (const float*)d_in[1];
    const float* Wq  = (const float*)d_in[2];
    const float* bq  = (const float*)d_in[3];
    const float* Wk  = (const float*)d_in[4];
    const float* bk  = (const float*)d_in[5];
    const float* Wv  = (const float*)d_in[6];
    const float* bv  = (const float*)d_in[7];
    const float* W1  = (const float*)d_in[8];
    const float* b1  = (const float*)d_in[9];
    const float* W2  = (const float*)d_in[10];
    const float* b2  = (const float*)d_in[11];
    float* out = (float*)d_out;

    float* h   = symaddr(g_h);
    float* q   = symaddr(g_q);
    float* k   = symaddr(g_k);
    float* v   = symaddr(g_v);
    float* sc  = symaddr(g_sc);
    float* mlp = symaddr(g_mlp);
    float* h2  = symaddr(g_h2);

    const float scale = 1.f / sqrtf((float)EDIM);

    // 1. embedding
    embed_kernel<<<NROWS, 256>>>(x, emb, h);

    // 2. QKV projections (N=8192, K=1024, Mo=1024)
    dim3 gproj(EDIM / BN, NROWS / BM, 1);
    gemm_nn<<<gproj, 256>>>(h, Wq, bq, q, NROWS, EDIM, EDIM, 0, 0, 0, 0, 1.f);
    gemm_nn<<<gproj, 256>>>(h, Wk, bk, k, NROWS, EDIM, EDIM, 0, 0, 0, 0, 1.f);
    gemm_nn<<<gproj, 256>>>(h, Wv, bv, v, NROWS, EDIM, EDIM, 0, 0, 0, 0, 1.f);

    // 3. scores = scale * q @ k^T  (batched over B)
    dim3 gsc(SEQ / BN, SEQ / BM, BATCH);
    gemm_nt<<<gsc, 256>>>(q, k, sc, SEQ, EDIM, SEQ,
                          (size_t)SEQ * EDIM, (size_t)SEQ * EDIM,
                          (size_t)SEQ * SEQ, scale);

    // 4. masked softmax (in place)
    dim3 gsm(SEQ, BATCH);
    softmax_kernel<<<gsm, 256>>>(sc);

    // 5. h2 = relu(w @ v)  (batched)
    dim3 gav(EDIM / BN, SEQ / BM, BATCH);
    gemm_nn<<<gav, 256>>>(sc, v, nullptr, h2, SEQ, SEQ, EDIM,
                          (size_t)SEQ * SEQ, (size_t)SEQ * EDIM,
                          (size_t)SEQ * EDIM, 1, 1.f);

    // 6. MLP stack (ping-pong h2 <-> h, last layer writes d_out)
    dim3 g1(MDIM / BN, NROWS / BM, 1);
    dim3 g2(EDIM / BN, NROWS / BM, 1);
    float* cur = h2;
    float* alt = h;
    for (int i = 0; i < NLAY; i++) {
        gemm_nn<<<g1, 256>>>(cur, W1 + (size_t)i * EDIM * MDIM, b1 + (size_t)i * MDIM,
                             mlp, NROWS, EDIM, MDIM, 0, 0, 0, 1, 1.f);
        float* dst = (i == NLAY - 1) ? out : alt;
        gemm_nn<<<g2, 256>>>(mlp, W2 + (size_t)i * MDIM * EDIM, b2 + (size_t)i * EDIM,
                             dst, NROWS, MDIM, EDIM, 0, 0, 0, 1, 1.f);
        float* t = cur; cur = alt; alt = t;
    }
}

// round 3
// speedup vs baseline: 2.3146x; 2.3146x over previous
#include <cuda_runtime.h>
#include <cuda_bf16.h>
#include <math.h>
#include <stdint.h>

// ---------------------------------------------------------------------------
// Problem constants
// ---------------------------------------------------------------------------
#define VOCAB 32000
#define EDIM  1024
#define MDIM  4096
#define NLAY  4
#define BATCH 4
#define SEQ   2048
#define NROWS (BATCH*SEQ)   // 8192

// ---------------------------------------------------------------------------
// Static device scratch (bf16 hi/lo split operands + fp32 intermediates)
// ---------------------------------------------------------------------------
__device__ __nv_bfloat16 g_hhi [NROWS * EDIM];
__device__ __nv_bfloat16 g_hlo [NROWS * EDIM];
__device__ __nv_bfloat16 g_qhi [NROWS * EDIM];
__device__ __nv_bfloat16 g_qlo [NROWS * EDIM];
__device__ __nv_bfloat16 g_khi [NROWS * EDIM];
__device__ __nv_bfloat16 g_klo [NROWS * EDIM];
__device__ float         g_v   [NROWS * EDIM];
__device__ __nv_bfloat16 g_vthi[(size_t)BATCH * EDIM * SEQ];
__device__ __nv_bfloat16 g_vtlo[(size_t)BATCH * EDIM * SEQ];
__device__ float         g_sc  [(size_t)BATCH * SEQ * SEQ];
__device__ __nv_bfloat16 g_whi [(size_t)BATCH * SEQ * SEQ];
__device__ __nv_bfloat16 g_wlo [(size_t)BATCH * SEQ * SEQ];
__device__ __nv_bfloat16 g_mhi [(size_t)NROWS * MDIM];
__device__ __nv_bfloat16 g_mlo [(size_t)NROWS * MDIM];
// transposed weights (hi|lo halves)
__device__ __nv_bfloat16 g_wqt [2 * EDIM * EDIM];
__device__ __nv_bfloat16 g_wkt [2 * EDIM * EDIM];
__device__ __nv_bfloat16 g_wvt [2 * EDIM * EDIM];
__device__ __nv_bfloat16 g_w1t [(size_t)2 * NLAY * MDIM * EDIM];
__device__ __nv_bfloat16 g_w2t [(size_t)2 * NLAY * EDIM * MDIM];

// ---------------------------------------------------------------------------
// PTX helpers (all valid at plain sm_103 / compute_103 target)
// ---------------------------------------------------------------------------
#define CP_ASYNC16(dst, src) \
    asm volatile("cp.async.cg.shared.global [%0], [%1], 16;" :: "r"(dst), "l"(src))
#define CP_COMMIT() asm volatile("cp.async.commit_group;" ::: "memory")
#define CP_WAIT(n)  asm volatile("cp.async.wait_group %0;" :: "n"(n) : "memory")

__device__ __forceinline__ uint32_t smem_u32(const void* p) {
    uint32_t a;
    asm("{ .reg .u64 t; cvta.to.shared.u64 t, %1; cvt.u32.u64 %0, t; }"
        : "=r"(a) : "l"(p));
    return a;
}

// mma.sync m16n8k16 bf16 -> f32, row.col
__device__ __forceinline__ void mma16816(float* c, const uint32_t* a, const uint32_t* b) {
    asm volatile(
        "mma.sync.aligned.m16n8k16.row.col.f32.bf16.bf16.f32 "
        "{%0,%1,%2,%3}, {%4,%5,%6,%7}, {%8,%9}, {%0,%1,%2,%3};"
        : "+f"(c[0]), "+f"(c[1]), "+f"(c[2]), "+f"(c[3])
        : "r"(a[0]), "r"(a[1]), "r"(a[2]), "r"(a[3]), "r"(b[0]), "r"(b[1]));
}

__device__ __forceinline__ void split2(float v, __nv_bfloat16& hi, __nv_bfloat16& lo) {
    hi = __float2bfloat16(v);
    lo = __float2bfloat16(v - __bfloat162float(hi));
}

// ---------------------------------------------------------------------------
// HMMA GEMM: out = act(scale*(Ahi+Alo)·(Bhi+Blo)^T + bias)
//   A [M,K] K-major, B [N,K] K-major (i.e., B already transposed).
//   CTA tile 128x128, 8 warps each 64x32, BK=32, 3-stage cp.async pipeline.
//   3 MMA passes into the same accumulator: Ahi·Bhi + Ahi·Blo + Alo·Bhi.
// ---------------------------------------------------------------------------
struct GP {
    const __nv_bfloat16 *Ahi, *Alo, *Bhi, *Blo;
    const float* bias;
    float* outF;
    __nv_bfloat16 *outHi, *outLo;
    int K, ldA, ldB, ldC;
    size_t szA, szB, szC;
    float scale;
    int relu;
    int maskSkip;
};

#define BK      32
#define APITCH  40                    // bf16 units per smem row (32 data + 8 pad)
#define TILEB   (128*APITCH*2)        // 10240 bytes per operand tile
#define STGB    (4*TILEB)             // 40960 bytes per stage (Ahi,Alo,Bhi,Blo)
#define NSTG    3
#define GEMM_SMEM (NSTG*STGB)         // 122880

__global__ void __launch_bounds__(256, 1) tgemm(GP p)
{
    const int m0 = blockIdx.y * 128;
    const int n0 = blockIdx.x * 128;
    if (p.maskSkip && (n0 + 128 <= m0)) return;

    extern __shared__ char smem[];
    const uint32_t sbase = smem_u32(smem);

    const int tid  = threadIdx.x;
    const int wid  = tid >> 5;
    const int lane = tid & 31;
    const int g    = lane >> 2;     // 0..7
    const int tg   = lane & 3;      // 0..3

    const int wm0 = (wid & 1) * 64;   // warp m offset in tile
    const int wn0 = (wid >> 1) * 32;  // warp n offset in tile

    const size_t zA = (size_t)blockIdx.z * p.szA;
    const size_t zB = (size_t)blockIdx.z * p.szB;
    const size_t zC = (size_t)blockIdx.z * p.szC;

    const char* aHi = (const char*)(p.Ahi + zA + (size_t)m0 * p.ldA);
    const char* aLo = (const char*)(p.Alo + zA + (size_t)m0 * p.ldA);
    const char* bHi = (const char*)(p.Bhi + zB + (size_t)n0 * p.ldB);
    const char* bLo = (const char*)(p.Blo + zB + (size_t)n0 * p.ldB);
    const size_t rsA = (size_t)p.ldA * 2;
    const size_t rsB = (size_t)p.ldB * 2;

    // per-thread load mapping: 512 chunks of 16B per operand tile
    const int ch_row0 = tid >> 2;          // chunk set 0: rows 0..63
    const int ch_c    = (tid & 3);         // 16B column 0..3
    const int NC = p.K / BK;

    auto load_chunk = [&](int c, int stg) {
        const size_t kb = (size_t)c * BK * 2;
        const uint32_t sb = sbase + stg * STGB;
        #pragma unroll
        for (int h = 0; h < 2; h++) {
            const int row = ch_row0 + h * 64;
            const uint32_t doff = row * (APITCH*2) + ch_c * 16;
            const size_t goffA = (size_t)row * rsA + kb + ch_c * 16;
            const size_t goffB = (size_t)row * rsB + kb + ch_c * 16;
            CP_ASYNC16(sb + 0*TILEB + doff, aHi + goffA);
            CP_ASYNC16(sb + 1*TILEB + doff, aLo + goffA);
            CP_ASYNC16(sb + 2*TILEB + doff, bHi + goffB);
            CP_ASYNC16(sb + 3*TILEB + doff, bLo + goffB);
        }
        CP_COMMIT();
    };

    float acc[4][4][4];
    #pragma unroll
    for (int i = 0; i < 4; i++)
        #pragma unroll
        for (int j = 0; j < 4; j++)
            #pragma unroll
            for (int q = 0; q < 4; q++) acc[i][j][q] = 0.f;

    load_chunk(0, 0);
    load_chunk(1, 1);
    load_chunk(2, 2);

    for (int c = 0; c < NC; c++) {
        const int stg = c % NSTG;
        const int ahead = NC - 1 - c;
        if (ahead >= 2)      CP_WAIT(2);
        else if (ahead == 1) CP_WAIT(1);
        else                 CP_WAIT(0);
        __syncthreads();

        const __nv_bfloat16* As_hi = (const __nv_bfloat16*)(smem + stg*STGB + 0*TILEB);
        const __nv_bfloat16* As_lo = (const __nv_bfloat16*)(smem + stg*STGB + 1*TILEB);
        const __nv_bfloat16* Bs_hi = (const __nv_bfloat16*)(smem + stg*STGB + 2*TILEB);
        const __nv_bfloat16* Bs_lo = (const __nv_bfloat16*)(smem + stg*STGB + 3*TILEB);

        #pragma unroll
        for (int kk = 0; kk < BK; kk += 16) {
            uint32_t ah[4][4], al[4][4], bh[4][2], bl[4][2];
            #pragma unroll
            for (int mt = 0; mt < 4; mt++) {
                const int r = wm0 + mt*16 + g;
                const int kc = kk + tg*2;
                ah[mt][0] = *(const uint32_t*)(As_hi + (size_t)r      * APITCH + kc);
                ah[mt][1] = *(const uint32_t*)(As_hi + (size_t)(r+8)  * APITCH + kc);
                ah[mt][2] = *(const uint32_t*)(As_hi + (size_t)r      * APITCH + kc + 8);
                ah[mt][3] = *(const uint32_t*)(As_hi + (size_t)(r+8)  * APITCH + kc + 8);
                al[mt][0] = *(const uint32_t*)(As_lo + (size_t)r      * APITCH + kc);
                al[mt][1] = *(const uint32_t*)(As_lo + (size_t)(r+8)  * APITCH + kc);
                al[mt][2] = *(const uint32_t*)(As_lo + (size_t)r      * APITCH + kc + 8);
                al[mt][3] = *(const uint32_t*)(As_lo + (size_t)(r+8)  * APITCH + kc + 8);
            }
            #pragma unroll
            for (int nt = 0; nt < 4; nt++) {
                const int r = wn0 + nt*8 + g;
                const int kc = kk + tg*2;
                bh[nt][0] = *(const uint32_t*)(Bs_hi + (size_t)r * APITCH + kc);
                bh[nt][1] = *(const uint32_t*)(Bs_hi + (size_t)r * APITCH + kc + 8);
                bl[nt][0] = *(const uint32_t*)(Bs_lo + (size_t)r * APITCH + kc);
                bl[nt][1] = *(const uint32_t*)(Bs_lo + (size_t)r * APITCH + kc + 8);
            }
            #pragma unroll
            for (int mt = 0; mt < 4; mt++)
                #pragma unroll
                for (int nt = 0; nt < 4; nt++) {
                    mma16816(acc[mt][nt], ah[mt], bh[nt]);
                    mma16816(acc[mt][nt], ah[mt], bl[nt]);
                    mma16816(acc[mt][nt], al[mt], bh[nt]);
                }
        }

        __syncthreads();
        if (c + NSTG < NC) load_chunk(c + NSTG, stg);
    }

    // ---- epilogue ----
    // bias values this thread needs: cols wn0+nt*8+tg*2 (+1)
    float2 bb[4];
    #pragma unroll
    for (int nt = 0; nt < 4; nt++) {
        if (p.bias) {
            const int cc = n0 + wn0 + nt*8 + tg*2;
            bb[nt] = *(const float2*)(p.bias + cc);
        } else bb[nt] = make_float2(0.f, 0.f);
    }

    #pragma unroll
    for (int mt = 0; mt < 4; mt++) {
        #pragma unroll
        for (int half = 0; half < 2; half++) {
            const int r = m0 + wm0 + mt*16 + g + half*8;
            #pragma unroll
            for (int nt = 0; nt < 4; nt++) {
                float x0 = acc[mt][nt][half*2+0] * p.scale + bb[nt].x;
                float x1 = acc[mt][nt][half*2+1] * p.scale + bb[nt].y;
                if (p.relu) { x0 = fmaxf(x0, 0.f); x1 = fmaxf(x1, 0.f); }
                const int cc = n0 + wn0 + nt*8 + tg*2;
                const size_t o = zC + (size_t)r * p.ldC + cc;
                if (p.outF)
                    *(float2*)(p.outF + o) = make_float2(x0, x1);
                if (p.outHi) {
                    __nv_bfloat16 h0, l0, h1, l1;
                    split2(x0, h0, l0);
                    split2(x1, h1, l1);
                    uint32_t hp = (uint32_t)__bfloat16_as_ushort(h0) |
                                  ((uint32_t)__bfloat16_as_ushort(h1) << 16);
                    uint32_t lp = (uint32_t)__bfloat16_as_ushort(l0) |
                                  ((uint32_t)__bfloat16_as_ushort(l1) << 16);
                    *(uint32_t*)(p.outHi + o) = hp;
                    *(uint32_t*)(p.outLo + o) = lp;
                }
            }
        }
    }
}

// ---------------------------------------------------------------------------
// Embedding gather + hi/lo split
// ---------------------------------------------------------------------------
__global__ void embed_split(const int* __restrict__ x, const float* __restrict__ emb,
                            __nv_bfloat16* __restrict__ hhi, __nv_bfloat16* __restrict__ hlo)
{
    const int r = blockIdx.x;
    const int row = x[r];
    const float4 f = ((const float4*)(emb + (size_t)row * EDIM))[threadIdx.x];
    const size_t o = (size_t)r * EDIM + threadIdx.x * 4;
    __nv_bfloat16 h, l;
    split2(f.x, h, l); hhi[o+0] = h; hlo[o+0] = l;
    split2(f.y, h, l); hhi[o+1] = h; hlo[o+1] = l;
    split2(f.z, h, l); hhi[o+2] = h; hlo[o+2] = l;
    split2(f.w, h, l); hhi[o+3] = h; hlo[o+3] = l;
}

// ---------------------------------------------------------------------------
// Transpose + hi/lo split: src fp32 [R,C] -> dst bf16 [C,R] (hi,lo)
// ---------------------------------------------------------------------------
__global__ void transpose_split(const float* __restrict__ src,
                                __nv_bfloat16* __restrict__ dhi,
                                __nv_bfloat16* __restrict__ dlo,
                                int R, int C, size_t szSrc, size_t szDst)
{
    __shared__ float t[32][33];
    src += (size_t)blockIdx.z * szSrc;
    dhi += (size_t)blockIdx.z * szDst;
    dlo += (size_t)blockIdx.z * szDst;
    const int c0 = blockIdx.x * 32, r0 = blockIdx.y * 32;
    const int tx = threadIdx.x, ty = threadIdx.y;
    #pragma unroll
    for (int j = 0; j < 4; j++)
        t[ty + j*8][tx] = src[(size_t)(r0 + ty + j*8) * C + c0 + tx];
    __syncthreads();
    #pragma unroll
    for (int j = 0; j < 4; j++) {
        const float v = t[tx][ty + j*8];
        __nv_bfloat16 h, l;
        split2(v, h, l);
        const size_t o = (size_t)(c0 + ty + j*8) * R + r0 + tx;
        dhi[o] = h; dlo[o] = l;
    }
}

// ---------------------------------------------------------------------------
// Masked softmax (keep t >= s), fp32 scores in -> bf16 hi/lo weights out
// ---------------------------------------------------------------------------
__global__ void __launch_bounds__(256) softmax_split(const float* __restrict__ sc,
                                                     __nv_bfloat16* __restrict__ whi,
                                                     __nv_bfloat16* __restrict__ wlo)
{
    const int s = blockIdx.x, b = blockIdx.y;
    const size_t base = ((size_t)b * SEQ + s) * SEQ;
    const float* row = sc + base;
    const int tid = threadIdx.x;
    __shared__ float red[256];

    float m = -1e30f;
    for (int t = s + tid; t < SEQ; t += 256) m = fmaxf(m, row[t]);
    red[tid] = m; __syncthreads();
    #pragma unroll
    for (int o = 128; o > 0; o >>= 1) {
        if (tid < o) red[tid] = fmaxf(red[tid], red[tid + o]);
        __syncthreads();
    }
    m = red[0]; __syncthreads();

    float sum = 0.f;
    for (int t = s + tid; t < SEQ; t += 256) sum += expf(row[t] - m);
    red[tid] = sum; __syncthreads();
    #pragma unroll
    for (int o = 128; o > 0; o >>= 1) {
        if (tid < o) red[tid] += red[tid + o];
        __syncthreads();
    }
    const float inv = 1.f / red[0];

    for (int t = tid; t < SEQ; t += 256) {
        const float w = (t < s) ? 0.f : expf(row[t] - m) * inv;
        __nv_bfloat16 h, l;
        split2(w, h, l);
        whi[base + t] = h; wlo[base + t] = l;
    }
}

// ---------------------------------------------------------------------------
// Host
// ---------------------------------------------------------------------------
template <typename T>
static T* sym(const void* s) { void* p = nullptr; cudaGetSymbolAddress(&p, s); return (T*)p; }

static void launch_gemm(GP& p, int M, int N, int Z)
{
    dim3 g(N / 128, M / 128, Z);
    tgemm<<<g, 256, GEMM_SMEM>>>(p);
}

extern "C" void kernel_launch(void* const* d_in, const int* in_sizes, int n_in,
                              void* d_out, int out_size)
{
    const int*   x   = (const int*)  d_in[0];
    const float* emb = (const float*)d_in[1];
    const float* Wq  = (const float*)d_in[2];
    const float* bq  = (const float*)d_in[3];
    const float* Wk  = (const float*)d_in[4];
    const float* bk  = (const float*)d_in[5];
    const float* Wv  = (const float*)d_in[6];
    const float* bv  = (const float*)d_in[7];
    const float* W1  = (const float*)d_in[8];
    const float* b1  = (const float*)d_in[9];
    const float* W2  = (const float*)d_in[10];
    const float* b2  = (const float*)d_in[11];
    float* out = (float*)d_out;

    cudaFuncSetAttribute(tgemm, cudaFuncAttributeMaxDynamicSharedMemorySize, GEMM_SMEM);

    __nv_bfloat16* hhi = sym<__nv_bfloat16>(g_hhi);
    __nv_bfloat16* hlo = sym<__nv_bfloat16>(g_hlo);
    __nv_bfloat16* qhi = sym<__nv_bfloat16>(g_qhi);
    __nv_bfloat16* qlo = sym<__nv_bfloat16>(g_qlo);
    __nv_bfloat16* khi = sym<__nv_bfloat16>(g_khi);
    __nv_bfloat16* klo = sym<__nv_bfloat16>(g_klo);
    float*         v   = sym<float>(g_v);
    __nv_bfloat16* vthi= sym<__nv_bfloat16>(g_vthi);
    __nv_bfloat16* vtlo= sym<__nv_bfloat16>(g_vtlo);
    float*         sc  = sym<float>(g_sc);
    __nv_bfloat16* whi = sym<__nv_bfloat16>(g_whi);
    __nv_bfloat16* wlo = sym<__nv_bfloat16>(g_wlo);
    __nv_bfloat16* mhi = sym<__nv_bfloat16>(g_mhi);
    __nv_bfloat16* mlo = sym<__nv_bfloat16>(g_mlo);
    __nv_bfloat16* wqt = sym<__nv_bfloat16>(g_wqt);
    __nv_bfloat16* wkt = sym<__nv_bfloat16>(g_wkt);
    __nv_bfloat16* wvt = sym<__nv_bfloat16>(g_wvt);
    __nv_bfloat16* w1t = sym<__nv_bfloat16>(g_w1t);
    __nv_bfloat16* w2t = sym<__nv_bfloat16>(g_w2t);

    const size_t EE = (size_t)EDIM * EDIM;
    const size_t EM = (size_t)EDIM * MDIM;

    // ---- weight transposes (to K-major hi/lo) ----
    dim3 tb(32, 8);
    transpose_split<<<dim3(EDIM/32, EDIM/32, 1), tb>>>(Wq, wqt, wqt + EE, EDIM, EDIM, 0, 0);
    transpose_split<<<dim3(EDIM/32, EDIM/32, 1), tb>>>(Wk, wkt, wkt + EE, EDIM, EDIM, 0, 0);
    transpose_split<<<dim3(EDIM/32, EDIM/32, 1), tb>>>(Wv, wvt, wvt + EE, EDIM, EDIM, 0, 0);
    transpose_split<<<dim3(MDIM/32, EDIM/32, NLAY), tb>>>(W1, w1t, w1t + (size_t)NLAY*EM, EDIM, MDIM, EM, EM);
    transpose_split<<<dim3(EDIM/32, MDIM/32, NLAY), tb>>>(W2, w2t, w2t + (size_t)NLAY*EM, MDIM, EDIM, EM, EM);

    // ---- embedding ----
    embed_split<<<NROWS, 256>>>(x, emb, hhi, hlo);

    // ---- QKV ----
    GP p = {};
    p.Ahi = hhi; p.Alo = hlo; p.ldA = EDIM; p.ldB = EDIM; p.ldC = EDIM;
    p.K = EDIM; p.scale = 1.f; p.relu = 0; p.maskSkip = 0;
    p.szA = p.szB = p.szC = 0;

    p.Bhi = wqt; p.Blo = wqt + EE; p.bias = bq;
    p.outHi = qhi; p.outLo = qlo; p.outF = nullptr;
    launch_gemm(p, NROWS, EDIM, 1);

    p.Bhi = wkt; p.Blo = wkt + EE; p.bias = bk;
    p.outHi = khi; p.outLo = klo;
    launch_gemm(p, NROWS, EDIM, 1);

    p.Bhi = wvt; p.Blo = wvt + EE; p.bias = bv;
    p.outHi = nullptr; p.outLo = nullptr; p.outF = v;
    launch_gemm(p, NROWS, EDIM, 1);

    // ---- v transpose per batch: [S,E] -> [E,S] ----
    transpose_split<<<dim3(EDIM/32, SEQ/32, BATCH), tb>>>(v, vthi, vtlo, SEQ, EDIM,
                                                          (size_t)SEQ*EDIM, (size_t)EDIM*SEQ);

    // ---- scores = scale * q k^T  (batched, masked-tile skip) ----
    p.Ahi = qhi; p.Alo = qlo; p.Bhi = khi; p.Blo = klo;
    p.ldA = EDIM; p.ldB = EDIM; p.ldC = SEQ; p.K = EDIM;
    p.szA = (size_t)SEQ * EDIM; p.szB = (size_t)SEQ * EDIM; p.szC = (size_t)SEQ * SEQ;
    p.bias = nullptr; p.outF = sc; p.outHi = nullptr; p.outLo = nullptr;
    p.scale = 1.f / 32.f; p.relu = 0; p.maskSkip = 1;
    launch_gemm(p, SEQ, SEQ, BATCH);

    // ---- softmax -> w hi/lo ----
    softmax_split<<<dim3(SEQ, BATCH), 256>>>(sc, whi, wlo);

    // ---- h = relu(w v)  (batched) ----
    p.Ahi = whi; p.Alo = wlo; p.Bhi = vthi; p.Blo = vtlo;
    p.ldA = SEQ; p.ldB = SEQ; p.ldC = EDIM; p.K = SEQ;
    p.szA = (size_t)SEQ * SEQ; p.szB = (size_t)EDIM * SEQ; p.szC = (size_t)SEQ * EDIM;
    p.bias = nullptr; p.outF = nullptr; p.outHi = hhi; p.outLo = hlo;
    p.scale = 1.f; p.relu = 1; p.maskSkip = 0;
    launch_gemm(p, SEQ, EDIM, BATCH);

    // ---- MLP stack (ping-pong h <-> q buffers) ----
    __nv_bfloat16 *curHi = hhi, *curLo = hlo;
    __nv_bfloat16 *altHi = qhi, *altLo = qlo;
    for (int i = 0; i < NLAY; i++) {
        p.Ahi = curHi; p.Alo = curLo;
        p.Bhi = w1t + (size_t)i * EM; p.Blo = w1t + (size_t)(NLAY + i) * EM;
        p.ldA = EDIM; p.ldB = EDIM; p.ldC = MDIM; p.K = EDIM;
        p.szA = p.szB = p.szC = 0;
        p.bias = b1 + (size_t)i * MDIM;
        p.outHi = mhi; p.outLo = mlo; p.outF = nullptr;
        p.scale = 1.f; p.relu = 1; p.maskSkip = 0;
        launch_gemm(p, NROWS, MDIM, 1);

        p.Ahi = mhi; p.Alo = mlo;
        p.Bhi = w2t + (size_t)i * EM; p.Blo = w2t + (size_t)(NLAY + i) * EM;
        p.ldA = MDIM; p.ldB = MDIM; p.ldC = EDIM; p.K = MDIM;
        p.bias = b2 + (size_t)i * EDIM;
        if (i == NLAY - 1) {
            p.outHi = nullptr; p.outLo = nullptr; p.outF = out;
        } else {
            p.outHi = altHi; p.outLo = altLo; p.outF = nullptr;
        }
        launch_gemm(p, NROWS, EDIM, 1);

        __nv_bfloat16* t;
        t = curHi; curHi = altHi; altHi = t;
        t = curLo; curLo = altLo; altLo = t;
    }
}

// round 4
// speedup vs baseline: 2.4777x; 1.0705x over previous
#include <cuda_runtime.h>
#include <cuda_bf16.h>
#include <math.h>
#include <stdint.h>

// ---------------------------------------------------------------------------
// Problem constants
// ---------------------------------------------------------------------------
#define VOCAB 32000
#define EDIM  1024
#define MDIM  4096
#define NLAY  4
#define BATCH 4
#define SEQ   2048
#define NROWS (BATCH*SEQ)   // 8192

// ---------------------------------------------------------------------------
// Static device scratch
// ---------------------------------------------------------------------------
__device__ __nv_bfloat16 g_hhi [NROWS * EDIM];
__device__ __nv_bfloat16 g_hlo [NROWS * EDIM];
__device__ __nv_bfloat16 g_qhi [NROWS * EDIM];
__device__ __nv_bfloat16 g_qlo [NROWS * EDIM];
__device__ __nv_bfloat16 g_khi [NROWS * EDIM];
__device__ __nv_bfloat16 g_klo [NROWS * EDIM];
__device__ float         g_v   [NROWS * EDIM];
__device__ __nv_bfloat16 g_vthi[(size_t)BATCH * EDIM * SEQ];
__device__ __nv_bfloat16 g_vtlo[(size_t)BATCH * EDIM * SEQ];
__device__ float         g_sc  [(size_t)BATCH * SEQ * SEQ];
__device__ __nv_bfloat16 g_whi [(size_t)BATCH * SEQ * SEQ];
__device__ __nv_bfloat16 g_wlo [(size_t)BATCH * SEQ * SEQ];
__device__ __nv_bfloat16 g_mhi [(size_t)NROWS * MDIM];
__device__ __nv_bfloat16 g_mlo [(size_t)NROWS * MDIM];
__device__ __nv_bfloat16 g_wqt [2 * EDIM * EDIM];
__device__ __nv_bfloat16 g_wkt [2 * EDIM * EDIM];
__device__ __nv_bfloat16 g_wvt [2 * EDIM * EDIM];
__device__ __nv_bfloat16 g_w1t [(size_t)2 * NLAY * MDIM * EDIM];
__device__ __nv_bfloat16 g_w2t [(size_t)2 * NLAY * EDIM * MDIM];

// ---------------------------------------------------------------------------
// PTX helpers (valid at plain compute_103 target)
// ---------------------------------------------------------------------------
#define CP_ASYNC16(dst, src) \
    asm volatile("cp.async.cg.shared.global [%0], [%1], 16;" :: "r"(dst), "l"(src))
#define CP_COMMIT() asm volatile("cp.async.commit_group;" ::: "memory")
#define CP_WAIT(n)  asm volatile("cp.async.wait_group %0;" :: "n"(n) : "memory")

__device__ __forceinline__ uint32_t smem_u32(const void* p) {
    uint32_t a;
    asm("{ .reg .u64 t; cvta.to.shared.u64 t, %1; cvt.u32.u64 %0, t; }"
        : "=r"(a) : "l"(p));
    return a;
}

#define LDSM4(R, A) \
    asm volatile("ldmatrix.sync.aligned.m8n8.x4.shared.b16 {%0,%1,%2,%3}, [%4];" \
        : "=r"((R)[0]), "=r"((R)[1]), "=r"((R)[2]), "=r"((R)[3]) : "r"(A))

__device__ __forceinline__ void mma16816(float* c, const uint32_t* a, const uint32_t* b) {
    asm volatile(
        "mma.sync.aligned.m16n8k16.row.col.f32.bf16.bf16.f32 "
        "{%0,%1,%2,%3}, {%4,%5,%6,%7}, {%8,%9}, {%0,%1,%2,%3};"
        : "+f"(c[0]), "+f"(c[1]), "+f"(c[2]), "+f"(c[3])
        : "r"(a[0]), "r"(a[1]), "r"(a[2]), "r"(a[3]), "r"(b[0]), "r"(b[1]));
}

__device__ __forceinline__ void split2(float v, __nv_bfloat16& hi, __nv_bfloat16& lo) {
    hi = __float2bfloat16(v);
    lo = __float2bfloat16(v - __bfloat162float(hi));
}

// ---------------------------------------------------------------------------
// HMMA GEMM: out = act(scale*(Ahi+Alo)·(Bhi+Blo)^T + bias)
//   A [M,K] K-major, B [N,K] K-major. CTA tile 128x128, 8 warps (64x32 each),
//   BK=32, 3-stage cp.async pipeline, ldmatrix fragments, pass-major MMA order.
// ---------------------------------------------------------------------------
struct GP {
    const __nv_bfloat16 *Ahi, *Alo, *Bhi, *Blo;
    const float* bias;
    float* outF;
    __nv_bfloat16 *outHi, *outLo;
    int K, ldA, ldB, ldC;
    size_t szA, szB, szC;
    float scale;
    int relu;
    int maskSkip;   // skip tiles fully below diagonal (scores)
    int triK;       // start K at m0 (w@v: w[s,t]=0 for t<s)
};

#define BK      32
#define APITCH  40                    // bf16 per smem row (32 data + 8 pad)
#define TILEB   (128*APITCH*2)        // 10240 B per operand tile
#define STGB    (4*TILEB)             // 40960 B per stage
#define NSTG    3
#define GEMM_SMEM (NSTG*STGB)         // 122880

__global__ void __launch_bounds__(256, 1) tgemm(GP p)
{
    const int m0 = blockIdx.y * 128;
    const int n0 = blockIdx.x * 128;
    if (p.maskSkip && (n0 + 128 <= m0)) return;

    extern __shared__ char smem[];
    const uint32_t sbase = smem_u32(smem);

    const int tid  = threadIdx.x;
    const int wid  = tid >> 5;
    const int lane = tid & 31;
    const int g    = lane >> 2;
    const int tg   = lane & 3;

    const int wm0 = (wid & 1) * 64;
    const int wn0 = (wid >> 1) * 32;

    const size_t zA = (size_t)blockIdx.z * p.szA;
    const size_t zB = (size_t)blockIdx.z * p.szB;
    const size_t zC = (size_t)blockIdx.z * p.szC;

    const char* aHi = (const char*)(p.Ahi + zA + (size_t)m0 * p.ldA);
    const char* aLo = (const char*)(p.Alo + zA + (size_t)m0 * p.ldA);
    const char* bHi = (const char*)(p.Bhi + zB + (size_t)n0 * p.ldB);
    const char* bLo = (const char*)(p.Blo + zB + (size_t)n0 * p.ldB);
    const size_t rsA = (size_t)p.ldA * 2;
    const size_t rsB = (size_t)p.ldB * 2;

    // ldmatrix lane address components
    const int l15 = lane & 15;
    const uint32_t aoff = (uint32_t)(((wm0 + l15) * APITCH + ((lane >> 4) * 8)) * 2);
    const int bN  = ((lane & 16) >> 1) + (lane & 7);      // n row within pair
    const uint32_t boff = (uint32_t)(((wn0 + bN) * APITCH + (lane & 8)) * 2);

    // cp.async mapping
    const int ch_row0 = tid >> 2;
    const int ch_c    = tid & 3;

    const int NC = p.K / BK;
    const int c0 = p.triK ? (m0 / BK) : 0;
    const int NCr = NC - c0;

    auto load_chunk = [&](int c, int stg) {
        const size_t kb = (size_t)c * BK * 2;
        const uint32_t sb = sbase + stg * STGB;
        #pragma unroll
        for (int h = 0; h < 2; h++) {
            const int row = ch_row0 + h * 64;
            const uint32_t doff = row * (APITCH*2) + ch_c * 16;
            const size_t goffA = (size_t)row * rsA + kb + ch_c * 16;
            const size_t goffB = (size_t)row * rsB + kb + ch_c * 16;
            CP_ASYNC16(sb + 0*TILEB + doff, aHi + goffA);
            CP_ASYNC16(sb + 1*TILEB + doff, aLo + goffA);
            CP_ASYNC16(sb + 2*TILEB + doff, bHi + goffB);
            CP_ASYNC16(sb + 3*TILEB + doff, bLo + goffB);
        }
        CP_COMMIT();
    };

    float acc[4][4][4];
    #pragma unroll
    for (int i = 0; i < 4; i++)
        #pragma unroll
        for (int j = 0; j < 4; j++)
            #pragma unroll
            for (int q = 0; q < 4; q++) acc[i][j][q] = 0.f;

    load_chunk(c0 + 0, 0);
    load_chunk(c0 + 1, 1);
    load_chunk(c0 + 2, 2);

    for (int cr = 0; cr < NCr; cr++) {
        const int stg = cr % NSTG;
        const int ahead = NCr - 1 - cr;
        if (ahead >= 2)      CP_WAIT(2);
        else if (ahead == 1) CP_WAIT(1);
        else                 CP_WAIT(0);
        __syncthreads();

        const uint32_t sb = sbase + stg * STGB;

        #pragma unroll
        for (int kk = 0; kk < BK; kk += 16) {
            uint32_t ah[4][4], al[4][4], bh[8], bl[8];
            #pragma unroll
            for (int mt = 0; mt < 4; mt++) {
                const uint32_t ao = sb + aoff + mt*(16*APITCH*2) + kk*2;
                LDSM4(ah[mt], ao);
                LDSM4(al[mt], ao + TILEB);
            }
            #pragma unroll
            for (int ntp = 0; ntp < 2; ntp++) {
                const uint32_t bo = sb + 2*TILEB + boff + ntp*(16*APITCH*2) + kk*2;
                LDSM4(&bh[ntp*4], bo);
                LDSM4(&bl[ntp*4], bo + TILEB);
            }
            // pass-major ordering: 16 independent MMAs between acc reuse
            #pragma unroll
            for (int mt = 0; mt < 4; mt++)
                #pragma unroll
                for (int nt = 0; nt < 4; nt++)
                    mma16816(acc[mt][nt], ah[mt], &bh[nt*2]);
            #pragma unroll
            for (int mt = 0; mt < 4; mt++)
                #pragma unroll
                for (int nt = 0; nt < 4; nt++)
                    mma16816(acc[mt][nt], ah[mt], &bl[nt*2]);
            #pragma unroll
            for (int mt = 0; mt < 4; mt++)
                #pragma unroll
                for (int nt = 0; nt < 4; nt++)
                    mma16816(acc[mt][nt], al[mt], &bh[nt*2]);
        }

        __syncthreads();
        if (cr + NSTG < NCr) load_chunk(c0 + cr + NSTG, stg);
    }

    // ---- epilogue ----
    float2 bb[4];
    #pragma unroll
    for (int nt = 0; nt < 4; nt++) {
        if (p.bias) {
            const int cc = n0 + wn0 + nt*8 + tg*2;
            bb[nt] = *(const float2*)(p.bias + cc);
        } else bb[nt] = make_float2(0.f, 0.f);
    }

    #pragma unroll
    for (int mt = 0; mt < 4; mt++) {
        #pragma unroll
        for (int half = 0; half < 2; half++) {
            const int r = m0 + wm0 + mt*16 + g + half*8;
            #pragma unroll
            for (int nt = 0; nt < 4; nt++) {
                float x0 = acc[mt][nt][half*2+0] * p.scale + bb[nt].x;
                float x1 = acc[mt][nt][half*2+1] * p.scale + bb[nt].y;
                if (p.relu) { x0 = fmaxf(x0, 0.f); x1 = fmaxf(x1, 0.f); }
                const int cc = n0 + wn0 + nt*8 + tg*2;
                const size_t o = zC + (size_t)r * p.ldC + cc;
                if (p.outF)
                    *(float2*)(p.outF + o) = make_float2(x0, x1);
                if (p.outHi) {
                    __nv_bfloat16 h0, l0, h1, l1;
                    split2(x0, h0, l0);
                    split2(x1, h1, l1);
                    uint32_t hp = (uint32_t)__bfloat16_as_ushort(h0) |
                                  ((uint32_t)__bfloat16_as_ushort(h1) << 16);
                    uint32_t lp = (uint32_t)__bfloat16_as_ushort(l0) |
                                  ((uint32_t)__bfloat16_as_ushort(l1) << 16);
                    *(uint32_t*)(p.outHi + o) = hp;
                    *(uint32_t*)(p.outLo + o) = lp;
                }
            }
        }
    }
}

// ---------------------------------------------------------------------------
// Embedding gather + hi/lo split
// ---------------------------------------------------------------------------
__global__ void embed_split(const int* __restrict__ x, const float* __restrict__ emb,
                            __nv_bfloat16* __restrict__ hhi, __nv_bfloat16* __restrict__ hlo)
{
    const int r = blockIdx.x;
    const int row = x[r];
    const float4 f = ((const float4*)(emb + (size_t)row * EDIM))[threadIdx.x];
    const size_t o = (size_t)r * EDIM + threadIdx.x * 4;
    __nv_bfloat16 h, l;
    split2(f.x, h, l); hhi[o+0] = h; hlo[o+0] = l;
    split2(f.y, h, l); hhi[o+1] = h; hlo[o+1] = l;
    split2(f.z, h, l); hhi[o+2] = h; hlo[o+2] = l;
    split2(f.w, h, l); hhi[o+3] = h; hlo[o+3] = l;
}

// ---------------------------------------------------------------------------
// Transpose + hi/lo split: src fp32 [R,C] -> dst bf16 [C,R] (hi,lo)
// ---------------------------------------------------------------------------
__global__ void transpose_split(const float* __restrict__ src,
                                __nv_bfloat16* __restrict__ dhi,
                                __nv_bfloat16* __restrict__ dlo,
                                int R, int C, size_t szSrc, size_t szDst)
{
    __shared__ float t[32][33];
    src += (size_t)blockIdx.z * szSrc;
    dhi += (size_t)blockIdx.z * szDst;
    dlo += (size_t)blockIdx.z * szDst;
    const int c0 = blockIdx.x * 32, r0 = blockIdx.y * 32;
    const int tx = threadIdx.x, ty = threadIdx.y;
    #pragma unroll
    for (int j = 0; j < 4; j++)
        t[ty + j*8][tx] = src[(size_t)(r0 + ty + j*8) * C + c0 + tx];
    __syncthreads();
    #pragma unroll
    for (int j = 0; j < 4; j++) {
        const float v = t[tx][ty + j*8];
        __nv_bfloat16 h, l;
        split2(v, h, l);
        const size_t o = (size_t)(c0 + ty + j*8) * R + r0 + tx;
        dhi[o] = h; dlo[o] = l;
    }
}

// ---------------------------------------------------------------------------
// Masked softmax (keep t >= s), fp32 in -> bf16 hi/lo out, exp cached in regs
// ---------------------------------------------------------------------------
__global__ void __launch_bounds__(256) softmax_split(const float* __restrict__ sc,
                                                     __nv_bfloat16* __restrict__ whi,
                                                     __nv_bfloat16* __restrict__ wlo)
{
    const int s = blockIdx.x, b = blockIdx.y;
    const size_t base = ((size_t)b * SEQ + s) * SEQ;
    const float* row = sc + base;
    const int tid = threadIdx.x;
    __shared__ float red[256];

    float m = -1e30f;
    for (int t = s + tid; t < SEQ; t += 256) m = fmaxf(m, row[t]);
    red[tid] = m; __syncthreads();
    #pragma unroll
    for (int o = 128; o > 0; o >>= 1) {
        if (tid < o) red[tid] = fmaxf(red[tid], red[tid + o]);
        __syncthreads();
    }
    m = red[0]; __syncthreads();

    float ev[8];
    float sum = 0.f;
    {
        int j = 0;
        for (int t = s + tid; t < SEQ; t += 256, j++) {
            const float e = expf(row[t] - m);
            ev[j] = e;
            sum += e;
        }
    }
    red[tid] = sum; __syncthreads();
    #pragma unroll
    for (int o = 128; o > 0; o >>= 1) {
        if (tid < o) red[tid] += red[tid + o];
        __syncthreads();
    }
    const float inv = 1.f / red[0];

    for (int t = tid; t < s; t += 256) {
        whi[base + t] = __float2bfloat16(0.f);
        wlo[base + t] = __float2bfloat16(0.f);
    }
    {
        int j = 0;
        for (int t = s + tid; t < SEQ; t += 256, j++) {
            __nv_bfloat16 h, l;
            split2(ev[j] * inv, h, l);
            whi[base + t] = h;
            wlo[base + t] = l;
        }
    }
}

// ---------------------------------------------------------------------------
// Host
// ---------------------------------------------------------------------------
template <typename T>
static T* sym(const void* s) { void* p = nullptr; cudaGetSymbolAddress(&p, s); return (T*)p; }

static void launch_gemm(GP& p, int M, int N, int Z)
{
    dim3 g(N / 128, M / 128, Z);
    tgemm<<<g, 256, GEMM_SMEM>>>(p);
}

extern "C" void kernel_launch(void* const* d_in, const int* in_sizes, int n_in,
                              void* d_out, int out_size)
{
    const int*   x   = (const int*)  d_in[0];
    const float* emb = (const float*)d_in[1];
    const float* Wq  = (const float*)d_in[2];
    const float* bq  = (const float*)d_in[3];
    const float* Wk  = (const float*)d_in[4];
    const float* bk  = (const float*)d_in[5];
    const float* Wv  = (const float*)d_in[6];
    const float* bv  = (const float*)d_in[7];
    const float* W1  = (const float*)d_in[8];
    const float* b1  = (const float*)d_in[9];
    const float* W2  = (const float*)d_in[10];
    const float* b2  = (const float*)d_in[11];
    float* out = (float*)d_out;

    cudaFuncSetAttribute(tgemm, cudaFuncAttributeMaxDynamicSharedMemorySize, GEMM_SMEM);

    __nv_bfloat16* hhi = sym<__nv_bfloat16>(g_hhi);
    __nv_bfloat16* hlo = sym<__nv_bfloat16>(g_hlo);
    __nv_bfloat16* qhi = sym<__nv_bfloat16>(g_qhi);
    __nv_bfloat16* qlo = sym<__nv_bfloat16>(g_qlo);
    __nv_bfloat16* khi = sym<__nv_bfloat16>(g_khi);
    __nv_bfloat16* klo = sym<__nv_bfloat16>(g_klo);
    float*         v   = sym<float>(g_v);
    __nv_bfloat16* vthi= sym<__nv_bfloat16>(g_vthi);
    __nv_bfloat16* vtlo= sym<__nv_bfloat16>(g_vtlo);
    float*         sc  = sym<float>(g_sc);
    __nv_bfloat16* whi = sym<__nv_bfloat16>(g_whi);
    __nv_bfloat16* wlo = sym<__nv_bfloat16>(g_wlo);
    __nv_bfloat16* mhi = sym<__nv_bfloat16>(g_mhi);
    __nv_bfloat16* mlo = sym<__nv_bfloat16>(g_mlo);
    __nv_bfloat16* wqt = sym<__nv_bfloat16>(g_wqt);
    __nv_bfloat16* wkt = sym<__nv_bfloat16>(g_wkt);
    __nv_bfloat16* wvt = sym<__nv_bfloat16>(g_wvt);
    __nv_bfloat16* w1t = sym<__nv_bfloat16>(g_w1t);
    __nv_bfloat16* w2t = sym<__nv_bfloat16>(g_w2t);

    const size_t EE = (size_t)EDIM * EDIM;
    const size_t EM = (size_t)EDIM * MDIM;

    dim3 tb(32, 8);
    transpose_split<<<dim3(EDIM/32, EDIM/32, 1), tb>>>(Wq, wqt, wqt + EE, EDIM, EDIM, 0, 0);
    transpose_split<<<dim3(EDIM/32, EDIM/32, 1), tb>>>(Wk, wkt, wkt + EE, EDIM, EDIM, 0, 0);
    transpose_split<<<dim3(EDIM/32, EDIM/32, 1), tb>>>(Wv, wvt, wvt + EE, EDIM, EDIM, 0, 0);
    transpose_split<<<dim3(MDIM/32, EDIM/32, NLAY), tb>>>(W1, w1t, w1t + (size_t)NLAY*EM, EDIM, MDIM, EM, EM);
    transpose_split<<<dim3(EDIM/32, MDIM/32, NLAY), tb>>>(W2, w2t, w2t + (size_t)NLAY*EM, MDIM, EDIM, EM, EM);

    embed_split<<<NROWS, 256>>>(x, emb, hhi, hlo);

    GP p = {};
    p.Ahi = hhi; p.Alo = hlo; p.ldA = EDIM; p.ldB = EDIM; p.ldC = EDIM;
    p.K = EDIM; p.scale = 1.f; p.relu = 0; p.maskSkip = 0; p.triK = 0;
    p.szA = p.szB = p.szC = 0;

    p.Bhi = wqt; p.Blo = wqt + EE; p.bias = bq;
    p.outHi = qhi; p.outLo = qlo; p.outF = nullptr;
    launch_gemm(p, NROWS, EDIM, 1);

    p.Bhi = wkt; p.Blo = wkt + EE; p.bias = bk;
    p.outHi = khi; p.outLo = klo;
    launch_gemm(p, NROWS, EDIM, 1);

    p.Bhi = wvt; p.Blo = wvt + EE; p.bias = bv;
    p.outHi = nullptr; p.outLo = nullptr; p.outF = v;
    launch_gemm(p, NROWS, EDIM, 1);

    transpose_split<<<dim3(EDIM/32, SEQ/32, BATCH), tb>>>(v, vthi, vtlo, SEQ, EDIM,
                                                          (size_t)SEQ*EDIM, (size_t)EDIM*SEQ);

    // scores = scale * q k^T  (batched, masked-tile skip)
    p.Ahi = qhi; p.Alo = qlo; p.Bhi = khi; p.Blo = klo;
    p.ldA = EDIM; p.ldB = EDIM; p.ldC = SEQ; p.K = EDIM;
    p.szA = (size_t)SEQ * EDIM; p.szB = (size_t)SEQ * EDIM; p.szC = (size_t)SEQ * SEQ;
    p.bias = nullptr; p.outF = sc; p.outHi = nullptr; p.outLo = nullptr;
    p.scale = 1.f / 32.f; p.relu = 0; p.maskSkip = 1; p.triK = 0;
    launch_gemm(p, SEQ, SEQ, BATCH);

    softmax_split<<<dim3(SEQ, BATCH), 256>>>(sc, whi, wlo);

    // h = relu(w v)  (batched, triangular K skip)
    p.Ahi = whi; p.Alo = wlo; p.Bhi = vthi; p.Blo = vtlo;
    p.ldA = SEQ; p.ldB = SEQ; p.ldC = EDIM; p.K = SEQ;
    p.szA = (size_t)SEQ * SEQ; p.szB = (size_t)EDIM * SEQ; p.szC = (size_t)SEQ * EDIM;
    p.bias = nullptr; p.outF = nullptr; p.outHi = hhi; p.outLo = hlo;
    p.scale = 1.f; p.relu = 1; p.maskSkip = 0; p.triK = 1;
    launch_gemm(p, SEQ, EDIM, BATCH);

    // MLP stack
    __nv_bfloat16 *curHi = hhi, *curLo = hlo;
    __nv_bfloat16 *altHi = qhi, *altLo = qlo;
    for (int i = 0; i < NLAY; i++) {
        p.Ahi = curHi; p.Alo = curLo;
        p.Bhi = w1t + (size_t)i * EM; p.Blo = w1t + (size_t)(NLAY + i) * EM;
        p.ldA = EDIM; p.ldB = EDIM; p.ldC = MDIM; p.K = EDIM;
        p.szA = p.szB = p.szC = 0;
        p.bias = b1 + (size_t)i * MDIM;
        p.outHi = mhi; p.outLo = mlo; p.outF = nullptr;
        p.scale = 1.f; p.relu = 1; p.maskSkip = 0; p.triK = 0;
        launch_gemm(p, NROWS, MDIM, 1);

        p.Ahi = mhi; p.Alo = mlo;
        p.Bhi = w2t + (size_t)i * EM; p.Blo = w2t + (size_t)(NLAY + i) * EM;
        p.ldA = MDIM; p.ldB = MDIM; p.ldC = EDIM; p.K = MDIM;
        p.bias = b2 + (size_t)i * EDIM;
        if (i == NLAY - 1) {
            p.outHi = nullptr; p.outLo = nullptr; p.outF = out;
        } else {
            p.outHi = altHi; p.outLo = altLo; p.outF = nullptr;
        }
        launch_gemm(p, NROWS, EDIM, 1);

        __nv_bfloat16* t;
        t = curHi; curHi = altHi; altHi = t;
        t = curLo; curLo = altLo; altLo = t;
    }
}

// round 5
// speedup vs baseline: 2.8109x; 1.1345x over previous
#include <cuda_runtime.h>
#include <cuda_bf16.h>
#include <math.h>
#include <stdint.h>

// ---------------------------------------------------------------------------
// Problem constants
// ---------------------------------------------------------------------------
#define VOCAB 32000
#define EDIM  1024
#define MDIM  4096
#define NLAY  4
#define BATCH 4
#define SEQ   2048
#define NROWS (BATCH*SEQ)   // 8192

// ---------------------------------------------------------------------------
// Static device scratch
// ---------------------------------------------------------------------------
__device__ __nv_bfloat16 g_hhi [NROWS * EDIM];
__device__ __nv_bfloat16 g_hlo [NROWS * EDIM];
__device__ __nv_bfloat16 g_qhi [NROWS * EDIM];
__device__ __nv_bfloat16 g_qlo [NROWS * EDIM];
__device__ __nv_bfloat16 g_khi [NROWS * EDIM];
__device__ __nv_bfloat16 g_klo [NROWS * EDIM];
__device__ float         g_v   [NROWS * EDIM];
__device__ __nv_bfloat16 g_vthi[(size_t)BATCH * EDIM * SEQ];
__device__ __nv_bfloat16 g_vtlo[(size_t)BATCH * EDIM * SEQ];
__device__ float         g_sc  [(size_t)BATCH * SEQ * SEQ];
__device__ __nv_bfloat16 g_whi [(size_t)BATCH * SEQ * SEQ];
__device__ __nv_bfloat16 g_wlo [(size_t)BATCH * SEQ * SEQ];
__device__ __nv_bfloat16 g_mhi [(size_t)NROWS * MDIM];
__device__ __nv_bfloat16 g_mlo [(size_t)NROWS * MDIM];
__device__ __nv_bfloat16 g_wqt [2 * EDIM * EDIM];
__device__ __nv_bfloat16 g_wkt [2 * EDIM * EDIM];
__device__ __nv_bfloat16 g_wvt [2 * EDIM * EDIM];
__device__ __nv_bfloat16 g_w1t [(size_t)2 * NLAY * MDIM * EDIM];
__device__ __nv_bfloat16 g_w2t [(size_t)2 * NLAY * EDIM * MDIM];

// ---------------------------------------------------------------------------
// PTX helpers (valid at plain compute_103 target)
// ---------------------------------------------------------------------------
#define CP_ASYNC16(dst, src) \
    asm volatile("cp.async.cg.shared.global [%0], [%1], 16;" :: "r"(dst), "l"(src))
#define CP_COMMIT() asm volatile("cp.async.commit_group;" ::: "memory")
#define CP_WAIT(n)  asm volatile("cp.async.wait_group %0;" :: "n"(n) : "memory")

__device__ __forceinline__ uint32_t smem_u32(const void* p) {
    uint32_t a;
    asm("{ .reg .u64 t; cvta.to.shared.u64 t, %1; cvt.u32.u64 %0, t; }"
        : "=r"(a) : "l"(p));
    return a;
}

#define LDSM4(R, A) \
    asm volatile("ldmatrix.sync.aligned.m8n8.x4.shared.b16 {%0,%1,%2,%3}, [%4];" \
        : "=r"((R)[0]), "=r"((R)[1]), "=r"((R)[2]), "=r"((R)[3]) : "r"(A))

__device__ __forceinline__ void mma16816(float* c, const uint32_t* a, const uint32_t* b) {
    asm volatile(
        "mma.sync.aligned.m16n8k16.row.col.f32.bf16.bf16.f32 "
        "{%0,%1,%2,%3}, {%4,%5,%6,%7}, {%8,%9}, {%0,%1,%2,%3};"
        : "+f"(c[0]), "+f"(c[1]), "+f"(c[2]), "+f"(c[3])
        : "r"(a[0]), "r"(a[1]), "r"(a[2]), "r"(a[3]), "r"(b[0]), "r"(b[1]));
}

__device__ __forceinline__ void split2(float v, __nv_bfloat16& hi, __nv_bfloat16& lo) {
    hi = __float2bfloat16(v);
    lo = __float2bfloat16(v - __bfloat162float(hi));
}

// ---------------------------------------------------------------------------
// HMMA GEMM: out = act(scale*(Ahi+Alo)·(Bhi+Blo)^T + bias)
//   A [M,K] K-major, B [N,K] K-major. CTA tile 128x128, 8 warps (64x32 each),
//   BK=64, 2-stage cp.async pipeline, ldmatrix fragments, pass-major MMA order.
// ---------------------------------------------------------------------------
struct GP {
    const __nv_bfloat16 *Ahi, *Alo, *Bhi, *Blo;
    const float* bias;
    float* outF;
    __nv_bfloat16 *outHi, *outLo;
    int K, ldA, ldB, ldC;
    size_t szA, szB, szC;
    float scale;
    int relu;
    int maskSkip;   // skip tiles fully below diagonal (scores)
    int triK;       // start K at m0 (w@v: w[s,t]=0 for t<s)
};

#define BK      64
#define APITCH  72                    // bf16 per smem row (64 data + 8 pad)
#define TILEB   (128*APITCH*2)        // 18432 B per operand tile
#define STGB    (4*TILEB)             // 73728 B per stage
#define NSTG    2
#define GEMM_SMEM (NSTG*STGB)         // 147456

__global__ void __launch_bounds__(256, 1) tgemm(GP p)
{
    const int m0 = blockIdx.y * 128;
    const int n0 = blockIdx.x * 128;
    if (p.maskSkip && (n0 + 128 <= m0)) return;

    extern __shared__ char smem[];
    const uint32_t sbase = smem_u32(smem);

    const int tid  = threadIdx.x;
    const int wid  = tid >> 5;
    const int lane = tid & 31;
    const int g    = lane >> 2;
    const int tg   = lane & 3;

    const int wm0 = (wid & 1) * 64;
    const int wn0 = (wid >> 1) * 32;

    const size_t zA = (size_t)blockIdx.z * p.szA;
    const size_t zB = (size_t)blockIdx.z * p.szB;
    const size_t zC = (size_t)blockIdx.z * p.szC;

    const char* aHi = (const char*)(p.Ahi + zA + (size_t)m0 * p.ldA);
    const char* aLo = (const char*)(p.Alo + zA + (size_t)m0 * p.ldA);
    const char* bHi = (const char*)(p.Bhi + zB + (size_t)n0 * p.ldB);
    const char* bLo = (const char*)(p.Blo + zB + (size_t)n0 * p.ldB);
    const size_t rsA = (size_t)p.ldA * 2;
    const size_t rsB = (size_t)p.ldB * 2;

    // ldmatrix lane address components
    const int l15 = lane & 15;
    const uint32_t aoff = (uint32_t)(((wm0 + l15) * APITCH + ((lane >> 4) * 8)) * 2);
    const int bN  = ((lane & 16) >> 1) + (lane & 7);
    const uint32_t boff = (uint32_t)(((wn0 + bN) * APITCH + (lane & 8)) * 2);

    // cp.async mapping: 128 rows x 128B per tile; 8 threads/row, 4 row-passes
    const int r0c = tid >> 3;
    const int ccc = (tid & 7) * 16;

    const int NC = p.K / BK;
    const int c0 = p.triK ? (m0 / BK) : 0;
    const int NCr = NC - c0;

    auto load_chunk = [&](int c, int stg) {
        const size_t kb = (size_t)c * BK * 2;
        const uint32_t sb = sbase + stg * STGB;
        #pragma unroll
        for (int h = 0; h < 4; h++) {
            const int row = r0c + h * 32;
            const uint32_t doff = row * (APITCH*2) + ccc;
            const size_t goA = (size_t)row * rsA + kb + ccc;
            const size_t goB = (size_t)row * rsB + kb + ccc;
            CP_ASYNC16(sb + 0*TILEB + doff, aHi + goA);
            CP_ASYNC16(sb + 1*TILEB + doff, aLo + goA);
            CP_ASYNC16(sb + 2*TILEB + doff, bHi + goB);
            CP_ASYNC16(sb + 3*TILEB + doff, bLo + goB);
        }
        CP_COMMIT();
    };

    float acc[4][4][4];
    #pragma unroll
    for (int i = 0; i < 4; i++)
        #pragma unroll
        for (int j = 0; j < 4; j++)
            #pragma unroll
            for (int q = 0; q < 4; q++) acc[i][j][q] = 0.f;

    load_chunk(c0 + 0, 0);
    load_chunk(c0 + 1, 1);

    for (int cr = 0; cr < NCr; cr++) {
        const int stg = cr & 1;
        if (cr + 1 < NCr) CP_WAIT(1);
        else              CP_WAIT(0);
        __syncthreads();

        const uint32_t sb = sbase + stg * STGB;

        #pragma unroll
        for (int kk = 0; kk < BK; kk += 16) {
            uint32_t ah[4][4], al[4][4], bh[8], bl[8];
            #pragma unroll
            for (int mt = 0; mt < 4; mt++) {
                const uint32_t ao = sb + aoff + mt*(16*APITCH*2) + kk*2;
                LDSM4(ah[mt], ao);
                LDSM4(al[mt], ao + TILEB);
            }
            #pragma unroll
            for (int ntp = 0; ntp < 2; ntp++) {
                const uint32_t bo = sb + 2*TILEB + boff + ntp*(16*APITCH*2) + kk*2;
                LDSM4(&bh[ntp*4], bo);
                LDSM4(&bl[ntp*4], bo + TILEB);
            }
            #pragma unroll
            for (int mt = 0; mt < 4; mt++)
                #pragma unroll
                for (int nt = 0; nt < 4; nt++)
                    mma16816(acc[mt][nt], ah[mt], &bh[nt*2]);
            #pragma unroll
            for (int mt = 0; mt < 4; mt++)
                #pragma unroll
                for (int nt = 0; nt < 4; nt++)
                    mma16816(acc[mt][nt], ah[mt], &bl[nt*2]);
            #pragma unroll
            for (int mt = 0; mt < 4; mt++)
                #pragma unroll
                for (int nt = 0; nt < 4; nt++)
                    mma16816(acc[mt][nt], al[mt], &bh[nt*2]);
        }

        __syncthreads();
        if (cr + NSTG < NCr) load_chunk(c0 + cr + NSTG, stg);
    }

    // ---- epilogue ----
    float2 bb[4];
    #pragma unroll
    for (int nt = 0; nt < 4; nt++) {
        if (p.bias) {
            const int cc = n0 + wn0 + nt*8 + tg*2;
            bb[nt] = *(const float2*)(p.bias + cc);
        } else bb[nt] = make_float2(0.f, 0.f);
    }

    #pragma unroll
    for (int mt = 0; mt < 4; mt++) {
        #pragma unroll
        for (int half = 0; half < 2; half++) {
            const int r = m0 + wm0 + mt*16 + g + half*8;
            #pragma unroll
            for (int nt = 0; nt < 4; nt++) {
                float x0 = acc[mt][nt][half*2+0] * p.scale + bb[nt].x;
                float x1 = acc[mt][nt][half*2+1] * p.scale + bb[nt].y;
                if (p.relu) { x0 = fmaxf(x0, 0.f); x1 = fmaxf(x1, 0.f); }
                const int cc = n0 + wn0 + nt*8 + tg*2;
                const size_t o = zC + (size_t)r * p.ldC + cc;
                if (p.outF)
                    *(float2*)(p.outF + o) = make_float2(x0, x1);
                if (p.outHi) {
                    __nv_bfloat16 h0, l0, h1, l1;
                    split2(x0, h0, l0);
                    split2(x1, h1, l1);
                    uint32_t hp = (uint32_t)__bfloat16_as_ushort(h0) |
                                  ((uint32_t)__bfloat16_as_ushort(h1) << 16);
                    uint32_t lp = (uint32_t)__bfloat16_as_ushort(l0) |
                                  ((uint32_t)__bfloat16_as_ushort(l1) << 16);
                    *(uint32_t*)(p.outHi + o) = hp;
                    *(uint32_t*)(p.outLo + o) = lp;
                }
            }
        }
    }
}

// ---------------------------------------------------------------------------
// Embedding gather + hi/lo split
// ---------------------------------------------------------------------------
__global__ void embed_split(const int* __restrict__ x, const float* __restrict__ emb,
                            __nv_bfloat16* __restrict__ hhi, __nv_bfloat16* __restrict__ hlo)
{
    const int r = blockIdx.x;
    const int row = x[r];
    const float4 f = ((const float4*)(emb + (size_t)row * EDIM))[threadIdx.x];
    const size_t o = (size_t)r * EDIM + threadIdx.x * 4;
    __nv_bfloat16 h, l;
    split2(f.x, h, l); hhi[o+0] = h; hlo[o+0] = l;
    split2(f.y, h, l); hhi[o+1] = h; hlo[o+1] = l;
    split2(f.z, h, l); hhi[o+2] = h; hlo[o+2] = l;
    split2(f.w, h, l); hhi[o+3] = h; hlo[o+3] = l;
}

// ---------------------------------------------------------------------------
// Transpose + hi/lo split: src fp32 [R,C] -> dst bf16 [C,R] (hi,lo)
// ---------------------------------------------------------------------------
__global__ void transpose_split(const float* __restrict__ src,
                                __nv_bfloat16* __restrict__ dhi,
                                __nv_bfloat16* __restrict__ dlo,
                                int R, int C, size_t szSrc, size_t szDst)
{
    __shared__ float t[32][33];
    src += (size_t)blockIdx.z * szSrc;
    dhi += (size_t)blockIdx.z * szDst;
    dlo += (size_t)blockIdx.z * szDst;
    const int c0 = blockIdx.x * 32, r0 = blockIdx.y * 32;
    const int tx = threadIdx.x, ty = threadIdx.y;
    #pragma unroll
    for (int j = 0; j < 4; j++)
        t[ty + j*8][tx] = src[(size_t)(r0 + ty + j*8) * C + c0 + tx];
    __syncthreads();
    #pragma unroll
    for (int j = 0; j < 4; j++) {
        const float v = t[tx][ty + j*8];
        __nv_bfloat16 h, l;
        split2(v, h, l);
        const size_t o = (size_t)(c0 + ty + j*8) * R + r0 + tx;
        dhi[o] = h; dlo[o] = l;
    }
}

// ---------------------------------------------------------------------------
// Masked softmax (keep t >= s), fp32 in -> bf16 hi/lo out, exp cached in regs
// ---------------------------------------------------------------------------
__global__ void __launch_bounds__(256) softmax_split(const float* __restrict__ sc,
                                                     __nv_bfloat16* __restrict__ whi,
                                                     __nv_bfloat16* __restrict__ wlo)
{
    const int s = blockIdx.x, b = blockIdx.y;
    const size_t base = ((size_t)b * SEQ + s) * SEQ;
    const float* row = sc + base;
    const int tid = threadIdx.x;
    __shared__ float red[256];

    float m = -1e30f;
    for (int t = s + tid; t < SEQ; t += 256) m = fmaxf(m, row[t]);
    red[tid] = m; __syncthreads();
    #pragma unroll
    for (int o = 128; o > 0; o >>= 1) {
        if (tid < o) red[tid] = fmaxf(red[tid], red[tid + o]);
        __syncthreads();
    }
    m = red[0]; __syncthreads();

    float ev[8];
    float sum = 0.f;
    {
        int j = 0;
        for (int t = s + tid; t < SEQ; t += 256, j++) {
            const float e = expf(row[t] - m);
            ev[j] = e;
            sum += e;
        }
    }
    red[tid] = sum; __syncthreads();
    #pragma unroll
    for (int o = 128; o > 0; o >>= 1) {
        if (tid < o) red[tid] += red[tid + o];
        __syncthreads();
    }
    const float inv = 1.f / red[0];

    for (int t = tid; t < s; t += 256) {
        whi[base + t] = __float2bfloat16(0.f);
        wlo[base + t] = __float2bfloat16(0.f);
    }
    {
        int j = 0;
        for (int t = s + tid; t < SEQ; t += 256, j++) {
            __nv_bfloat16 h, l;
            split2(ev[j] * inv, h, l);
            whi[base + t] = h;
            wlo[base + t] = l;
        }
    }
}

// ---------------------------------------------------------------------------
// Host
// ---------------------------------------------------------------------------
template <typename T>
static T* sym(const void* s) { void* p = nullptr; cudaGetSymbolAddress(&p, s); return (T*)p; }

static void launch_gemm(GP& p, int M, int N, int Z)
{
    dim3 g(N / 128, M / 128, Z);
    tgemm<<<g, 256, GEMM_SMEM>>>(p);
}

extern "C" void kernel_launch(void* const* d_in, const int* in_sizes, int n_in,
                              void* d_out, int out_size)
{
    const int*   x   = (const int*)  d_in[0];
    const float* emb = (const float*)d_in[1];
    const float* Wq  = (const float*)d_in[2];
    const float* bq  = (const float*)d_in[3];
    const float* Wk  = (const float*)d_in[4];
    const float* bk  = (const float*)d_in[5];
    const float* Wv  = (const float*)d_in[6];
    const float* bv  = (const float*)d_in[7];
    const float* W1  = (const float*)d_in[8];
    const float* b1  = (const float*)d_in[9];
    const float* W2  = (const float*)d_in[10];
    const float* b2  = (const float*)d_in[11];
    float* out = (float*)d_out;

    cudaFuncSetAttribute(tgemm, cudaFuncAttributeMaxDynamicSharedMemorySize, GEMM_SMEM);

    __nv_bfloat16* hhi = sym<__nv_bfloat16>(g_hhi);
    __nv_bfloat16* hlo = sym<__nv_bfloat16>(g_hlo);
    __nv_bfloat16* qhi = sym<__nv_bfloat16>(g_qhi);
    __nv_bfloat16* qlo = sym<__nv_bfloat16>(g_qlo);
    __nv_bfloat16* khi = sym<__nv_bfloat16>(g_khi);
    __nv_bfloat16* klo = sym<__nv_bfloat16>(g_klo);
    float*         v   = sym<float>(g_v);
    __nv_bfloat16* vthi= sym<__nv_bfloat16>(g_vthi);
    __nv_bfloat16* vtlo= sym<__nv_bfloat16>(g_vtlo);
    float*         sc  = sym<float>(g_sc);
    __nv_bfloat16* whi = sym<__nv_bfloat16>(g_whi);
    __nv_bfloat16* wlo = sym<__nv_bfloat16>(g_wlo);
    __nv_bfloat16* mhi = sym<__nv_bfloat16>(g_mhi);
    __nv_bfloat16* mlo = sym<__nv_bfloat16>(g_mlo);
    __nv_bfloat16* wqt = sym<__nv_bfloat16>(g_wqt);
    __nv_bfloat16* wkt = sym<__nv_bfloat16>(g_wkt);
    __nv_bfloat16* wvt = sym<__nv_bfloat16>(g_wvt);
    __nv_bfloat16* w1t = sym<__nv_bfloat16>(g_w1t);
    __nv_bfloat16* w2t = sym<__nv_bfloat16>(g_w2t);

    const size_t EE = (size_t)EDIM * EDIM;
    const size_t EM = (size_t)EDIM * MDIM;

    dim3 tb(32, 8);
    transpose_split<<<dim3(EDIM/32, EDIM/32, 1), tb>>>(Wq, wqt, wqt + EE, EDIM, EDIM, 0, 0);
    transpose_split<<<dim3(EDIM/32, EDIM/32, 1), tb>>>(Wk, wkt, wkt + EE, EDIM, EDIM, 0, 0);
    transpose_split<<<dim3(EDIM/32, EDIM/32, 1), tb>>>(Wv, wvt, wvt + EE, EDIM, EDIM, 0, 0);
    transpose_split<<<dim3(MDIM/32, EDIM/32, NLAY), tb>>>(W1, w1t, w1t + (size_t)NLAY*EM, EDIM, MDIM, EM, EM);
    transpose_split<<<dim3(EDIM/32, MDIM/32, NLAY), tb>>>(W2, w2t, w2t + (size_t)NLAY*EM, MDIM, EDIM, EM, EM);

    embed_split<<<NROWS, 256>>>(x, emb, hhi, hlo);

    GP p = {};
    p.Ahi = hhi; p.Alo = hlo; p.ldA = EDIM; p.ldB = EDIM; p.ldC = EDIM;
    p.K = EDIM; p.scale = 1.f; p.relu = 0; p.maskSkip = 0; p.triK = 0;
    p.szA = p.szB = p.szC = 0;

    p.Bhi = wqt; p.Blo = wqt + EE; p.bias = bq;
    p.outHi = qhi; p.outLo = qlo; p.outF = nullptr;
    launch_gemm(p, NROWS, EDIM, 1);

    p.Bhi = wkt; p.Blo = wkt + EE; p.bias = bk;
    p.outHi = khi; p.outLo = klo;
    launch_gemm(p, NROWS, EDIM, 1);

    p.Bhi = wvt; p.Blo = wvt + EE; p.bias = bv;
    p.outHi = nullptr; p.outLo = nullptr; p.outF = v;
    launch_gemm(p, NROWS, EDIM, 1);

    transpose_split<<<dim3(EDIM/32, SEQ/32, BATCH), tb>>>(v, vthi, vtlo, SEQ, EDIM,
                                                          (size_t)SEQ*EDIM, (size_t)EDIM*SEQ);

    // scores = scale * q k^T  (batched, masked-tile skip)
    p.Ahi = qhi; p.Alo = qlo; p.Bhi = khi; p.Blo = klo;
    p.ldA = EDIM; p.ldB = EDIM; p.ldC = SEQ; p.K = EDIM;
    p.szA = (size_t)SEQ * EDIM; p.szB = (size_t)SEQ * EDIM; p.szC = (size_t)SEQ * SEQ;
    p.bias = nullptr; p.outF = sc; p.outHi = nullptr; p.outLo = nullptr;
    p.scale = 1.f / 32.f; p.relu = 0; p.maskSkip = 1; p.triK = 0;
    launch_gemm(p, SEQ, SEQ, BATCH);

    softmax_split<<<dim3(SEQ, BATCH), 256>>>(sc, whi, wlo);

    // h = relu(w v)  (batched, triangular K skip)
    p.Ahi = whi; p.Alo = wlo; p.Bhi = vthi; p.Blo = vtlo;
    p.ldA = SEQ; p.ldB = SEQ; p.ldC = EDIM; p.K = SEQ;
    p.szA = (size_t)SEQ * SEQ; p.szB = (size_t)EDIM * SEQ; p.szC = (size_t)SEQ * EDIM;
    p.bias = nullptr; p.outF = nullptr; p.outHi = hhi; p.outLo = hlo;
    p.scale = 1.f; p.relu = 1; p.maskSkip = 0; p.triK = 1;
    launch_gemm(p, SEQ, EDIM, BATCH);

    // MLP stack
    __nv_bfloat16 *curHi = hhi, *curLo = hlo;
    __nv_bfloat16 *altHi = qhi, *altLo = qlo;
    for (int i = 0; i < NLAY; i++) {
        p.Ahi = curHi; p.Alo = curLo;
        p.Bhi = w1t + (size_t)i * EM; p.Blo = w1t + (size_t)(NLAY + i) * EM;
        p.ldA = EDIM; p.ldB = EDIM; p.ldC = MDIM; p.K = EDIM;
        p.szA = p.szB = p.szC = 0;
        p.bias = b1 + (size_t)i * MDIM;
        p.outHi = mhi; p.outLo = mlo; p.outF = nullptr;
        p.scale = 1.f; p.relu = 1; p.maskSkip = 0; p.triK = 0;
        launch_gemm(p, NROWS, MDIM, 1);

        p.Ahi = mhi; p.Alo = mlo;
        p.Bhi = w2t + (size_t)i * EM; p.Blo = w2t + (size_t)(NLAY + i) * EM;
        p.ldA = MDIM; p.ldB = MDIM; p.ldC = EDIM; p.K = MDIM;
        p.bias = b2 + (size_t)i * EDIM;
        if (i == NLAY - 1) {
            p.outHi = nullptr; p.outLo = nullptr; p.outF = out;
        } else {
            p.outHi = altHi; p.outLo = altLo; p.outF = nullptr;
        }
        launch_gemm(p, NROWS, EDIM, 1);

        __nv_bfloat16* t;
        t = curHi; curHi = altHi; altHi = t;
        t = curLo; curLo = altLo; altLo = t;
    }
}

// round 6
// speedup vs baseline: 3.0316x; 1.0785x over previous
#include <cuda_runtime.h>
#include <cuda_bf16.h>
#include <math.h>
#include <stdint.h>

// ---------------------------------------------------------------------------
// Problem constants
// ---------------------------------------------------------------------------
#define VOCAB 32000
#define EDIM  1024
#define MDIM  4096
#define NLAY  4
#define BATCH 4
#define SEQ   2048
#define NROWS (BATCH*SEQ)   // 8192

// ---------------------------------------------------------------------------
// Static device scratch
// ---------------------------------------------------------------------------
__device__ __nv_bfloat16 g_hhi [NROWS * EDIM];
__device__ __nv_bfloat16 g_hlo [NROWS * EDIM];
__device__ __nv_bfloat16 g_qhi [NROWS * EDIM];
__device__ __nv_bfloat16 g_qlo [NROWS * EDIM];
__device__ __nv_bfloat16 g_khi [NROWS * EDIM];
__device__ __nv_bfloat16 g_klo [NROWS * EDIM];
__device__ float         g_v   [NROWS * EDIM];
__device__ __nv_bfloat16 g_vthi[(size_t)BATCH * EDIM * SEQ];
__device__ __nv_bfloat16 g_vtlo[(size_t)BATCH * EDIM * SEQ];
__device__ float         g_sc  [(size_t)BATCH * SEQ * SEQ];
__device__ __nv_bfloat16 g_whi [(size_t)BATCH * SEQ * SEQ];
__device__ __nv_bfloat16 g_wlo [(size_t)BATCH * SEQ * SEQ];
__device__ __nv_bfloat16 g_mhi [(size_t)NROWS * MDIM];
__device__ __nv_bfloat16 g_mlo [(size_t)NROWS * MDIM];
__device__ __nv_bfloat16 g_wqt [2 * EDIM * EDIM];
__device__ __nv_bfloat16 g_wkt [2 * EDIM * EDIM];
__device__ __nv_bfloat16 g_wvt [2 * EDIM * EDIM];
__device__ __nv_bfloat16 g_w1t [(size_t)2 * NLAY * MDIM * EDIM];
__device__ __nv_bfloat16 g_w2t [(size_t)2 * NLAY * EDIM * MDIM];

// ---------------------------------------------------------------------------
// PTX helpers (valid at plain compute_103 target)
// ---------------------------------------------------------------------------
#define CP_ASYNC16(dst, src) \
    asm volatile("cp.async.cg.shared.global [%0], [%1], 16;" :: "r"(dst), "l"(src))
#define CP_COMMIT() asm volatile("cp.async.commit_group;" ::: "memory")
#define CP_WAIT(n)  asm volatile("cp.async.wait_group %0;" :: "n"(n) : "memory")

__device__ __forceinline__ uint32_t smem_u32(const void* p) {
    uint32_t a;
    asm("{ .reg .u64 t; cvta.to.shared.u64 t, %1; cvt.u32.u64 %0, t; }"
        : "=r"(a) : "l"(p));
    return a;
}

#define LDSM4(R, A) \
    asm volatile("ldmatrix.sync.aligned.m8n8.x4.shared.b16 {%0,%1,%2,%3}, [%4];" \
        : "=r"((R)[0]), "=r"((R)[1]), "=r"((R)[2]), "=r"((R)[3]) : "r"(A))

__device__ __forceinline__ void mma16816(float* c, const uint32_t* a, const uint32_t* b) {
    asm volatile(
        "mma.sync.aligned.m16n8k16.row.col.f32.bf16.bf16.f32 "
        "{%0,%1,%2,%3}, {%4,%5,%6,%7}, {%8,%9}, {%0,%1,%2,%3};"
        : "+f"(c[0]), "+f"(c[1]), "+f"(c[2]), "+f"(c[3])
        : "r"(a[0]), "r"(a[1]), "r"(a[2]), "r"(a[3]), "r"(b[0]), "r"(b[1]));
}

__device__ __forceinline__ void split2(float v, __nv_bfloat16& hi, __nv_bfloat16& lo) {
    hi = __float2bfloat16(v);
    lo = __float2bfloat16(v - __bfloat162float(hi));
}

// ---------------------------------------------------------------------------
// HMMA GEMM: out = act(scale*(Ahi+Alo)·(Bhi+Blo)^T + bias)
//   A [M,K] K-major, B [N,K] K-major. CTA tile 128x256, 8 warps (64x64 each),
//   BK=64, 2-stage cp.async pipeline, ldmatrix, pass-major MMA order.
// ---------------------------------------------------------------------------
struct GP {
    const __nv_bfloat16 *Ahi, *Alo, *Bhi, *Blo;
    const float* bias;
    float* outF;
    __nv_bfloat16 *outHi, *outLo;
    int K, ldA, ldB, ldC;
    size_t szA, szB, szC;
    float scale;
    int relu;
    int maskSkip;   // skip tiles fully below diagonal (scores)
    int triK;       // start K at m0 (w@v: w[s,t]=0 for t<s)
};

#define BK      64
#define APITCH  72                    // bf16 per smem row (64 data + 8 pad)
#define TILEA   (128*APITCH*2)        // 18432 B  (A hi or lo)
#define TILEBB  (256*APITCH*2)        // 36864 B  (B hi or lo)
#define STGB    (2*TILEA + 2*TILEBB)  // 110592 B per stage
#define NSTG    2
#define GEMM_SMEM (NSTG*STGB)         // 221184 B

// stage-internal offsets
#define OFF_AHI 0
#define OFF_ALO (TILEA)
#define OFF_BHI (2*TILEA)
#define OFF_BLO (2*TILEA + TILEBB)

__global__ void __launch_bounds__(256, 1) tgemm(GP p)
{
    const int m0 = blockIdx.y * 128;
    const int n0 = blockIdx.x * 256;
    if (p.maskSkip && (n0 + 256 <= m0)) return;

    extern __shared__ char smem[];
    const uint32_t sbase = smem_u32(smem);

    const int tid  = threadIdx.x;
    const int wid  = tid >> 5;
    const int lane = tid & 31;
    const int g    = lane >> 2;
    const int tg   = lane & 3;

    const int wm0 = (wid & 1) * 64;      // warp m offset (0/64)
    const int wn0 = (wid >> 1) * 64;     // warp n offset (0/64/128/192)

    const size_t zA = (size_t)blockIdx.z * p.szA;
    const size_t zB = (size_t)blockIdx.z * p.szB;
    const size_t zC = (size_t)blockIdx.z * p.szC;

    const char* aHi = (const char*)(p.Ahi + zA + (size_t)m0 * p.ldA);
    const char* aLo = (const char*)(p.Alo + zA + (size_t)m0 * p.ldA);
    const char* bHi = (const char*)(p.Bhi + zB + (size_t)n0 * p.ldB);
    const char* bLo = (const char*)(p.Blo + zB + (size_t)n0 * p.ldB);
    const size_t rsA = (size_t)p.ldA * 2;
    const size_t rsB = (size_t)p.ldB * 2;

    // ldmatrix lane address components
    const int l15 = lane & 15;
    const uint32_t aoff = (uint32_t)(((wm0 + l15) * APITCH + ((lane >> 4) * 8)) * 2);
    const int bN  = ((lane & 16) >> 1) + (lane & 7);
    const uint32_t boff = (uint32_t)(((wn0 + bN) * APITCH + (lane & 8)) * 2);

    // cp.async mapping: 8 threads/row (128B), 256 threads -> 32 rows/pass
    const int r0c = tid >> 3;
    const int ccc = (tid & 7) * 16;

    const int NC = p.K / BK;
    const int c0 = p.triK ? (m0 / BK) : 0;
    const int NCr = NC - c0;

    auto load_chunk = [&](int c, int stg) {
        const size_t kb = (size_t)c * BK * 2;
        const uint32_t sb = sbase + stg * STGB;
        #pragma unroll
        for (int h = 0; h < 4; h++) {            // A: 128 rows
            const int row = r0c + h * 32;
            const uint32_t doff = row * (APITCH*2) + ccc;
            const size_t goA = (size_t)row * rsA + kb + ccc;
            CP_ASYNC16(sb + OFF_AHI + doff, aHi + goA);
            CP_ASYNC16(sb + OFF_ALO + doff, aLo + goA);
        }
        #pragma unroll
        for (int h = 0; h < 8; h++) {            // B: 256 rows
            const int row = r0c + h * 32;
            const uint32_t doff = row * (APITCH*2) + ccc;
            const size_t goB = (size_t)row * rsB + kb + ccc;
            CP_ASYNC16(sb + OFF_BHI + doff, bHi + goB);
            CP_ASYNC16(sb + OFF_BLO + doff, bLo + goB);
        }
        CP_COMMIT();
    };

    float acc[4][8][4];
    #pragma unroll
    for (int i = 0; i < 4; i++)
        #pragma unroll
        for (int j = 0; j < 8; j++)
            #pragma unroll
            for (int q = 0; q < 4; q++) acc[i][j][q] = 0.f;

    load_chunk(c0 + 0, 0);
    load_chunk(c0 + 1, 1);

    for (int cr = 0; cr < NCr; cr++) {
        const int stg = cr & 1;
        if (cr + 1 < NCr) CP_WAIT(1);
        else              CP_WAIT(0);
        __syncthreads();

        const uint32_t sb = sbase + stg * STGB;

        #pragma unroll
        for (int kk = 0; kk < BK; kk += 16) {
            uint32_t ah[4][4], al[4][4];
            #pragma unroll
            for (int mt = 0; mt < 4; mt++) {
                const uint32_t ao = sb + aoff + mt*(16*APITCH*2) + kk*2;
                LDSM4(ah[mt], ao);
                LDSM4(al[mt], ao + TILEA);
            }
            #pragma unroll
            for (int ntp = 0; ntp < 4; ntp++) {   // 16 n-cols per group
                uint32_t bh[4], bl[4];
                const uint32_t bo = sb + OFF_BHI + boff + ntp*(16*APITCH*2) + kk*2;
                LDSM4(bh, bo);
                LDSM4(bl, bo + TILEBB);
                // pass-major: 8 independent MMAs between acc reuse
                #pragma unroll
                for (int mt = 0; mt < 4; mt++)
                    #pragma unroll
                    for (int nt = 0; nt < 2; nt++)
                        mma16816(acc[mt][ntp*2+nt], ah[mt], &bh[nt*2]);
                #pragma unroll
                for (int mt = 0; mt < 4; mt++)
                    #pragma unroll
                    for (int nt = 0; nt < 2; nt++)
                        mma16816(acc[mt][ntp*2+nt], ah[mt], &bl[nt*2]);
                #pragma unroll
                for (int mt = 0; mt < 4; mt++)
                    #pragma unroll
                    for (int nt = 0; nt < 2; nt++)
                        mma16816(acc[mt][ntp*2+nt], al[mt], &bh[nt*2]);
            }
        }

        __syncthreads();
        if (cr + NSTG < NCr) load_chunk(c0 + cr + NSTG, stg);
    }

    // ---- epilogue ----
    float2 bb[8];
    #pragma unroll
    for (int nt = 0; nt < 8; nt++) {
        if (p.bias) {
            const int cc = n0 + wn0 + nt*8 + tg*2;
            bb[nt] = *(const float2*)(p.bias + cc);
        } else bb[nt] = make_float2(0.f, 0.f);
    }

    #pragma unroll
    for (int mt = 0; mt < 4; mt++) {
        #pragma unroll
        for (int half = 0; half < 2; half++) {
            const int r = m0 + wm0 + mt*16 + g + half*8;
            #pragma unroll
            for (int nt = 0; nt < 8; nt++) {
                float x0 = acc[mt][nt][half*2+0] * p.scale + bb[nt].x;
                float x1 = acc[mt][nt][half*2+1] * p.scale + bb[nt].y;
                if (p.relu) { x0 = fmaxf(x0, 0.f); x1 = fmaxf(x1, 0.f); }
                const int cc = n0 + wn0 + nt*8 + tg*2;
                const size_t o = zC + (size_t)r * p.ldC + cc;
                if (p.outF)
                    *(float2*)(p.outF + o) = make_float2(x0, x1);
                if (p.outHi) {
                    __nv_bfloat16 h0, l0, h1, l1;
                    split2(x0, h0, l0);
                    split2(x1, h1, l1);
                    uint32_t hp = (uint32_t)__bfloat16_as_ushort(h0) |
                                  ((uint32_t)__bfloat16_as_ushort(h1) << 16);
                    uint32_t lp = (uint32_t)__bfloat16_as_ushort(l0) |
                                  ((uint32_t)__bfloat16_as_ushort(l1) << 16);
                    *(uint32_t*)(p.outHi + o) = hp;
                    *(uint32_t*)(p.outLo + o) = lp;
                }
            }
        }
    }
}

// ---------------------------------------------------------------------------
// Embedding gather + hi/lo split
// ---------------------------------------------------------------------------
__global__ void embed_split(const int* __restrict__ x, const float* __restrict__ emb,
                            __nv_bfloat16* __restrict__ hhi, __nv_bfloat16* __restrict__ hlo)
{
    const int r = blockIdx.x;
    const int row = x[r];
    const float4 f = ((const float4*)(emb + (size_t)row * EDIM))[threadIdx.x];
    const size_t o = (size_t)r * EDIM + threadIdx.x * 4;
    __nv_bfloat16 h, l;
    split2(f.x, h, l); hhi[o+0] = h; hlo[o+0] = l;
    split2(f.y, h, l); hhi[o+1] = h; hlo[o+1] = l;
    split2(f.z, h, l); hhi[o+2] = h; hlo[o+2] = l;
    split2(f.w, h, l); hhi[o+3] = h; hlo[o+3] = l;
}

// ---------------------------------------------------------------------------
// Transpose + hi/lo split: src fp32 [R,C] -> dst bf16 [C,R] (hi,lo)
// ---------------------------------------------------------------------------
__global__ void transpose_split(const float* __restrict__ src,
                                __nv_bfloat16* __restrict__ dhi,
                                __nv_bfloat16* __restrict__ dlo,
                                int R, int C, size_t szSrc, size_t szDst)
{
    __shared__ float t[32][33];
    src += (size_t)blockIdx.z * szSrc;
    dhi += (size_t)blockIdx.z * szDst;
    dlo += (size_t)blockIdx.z * szDst;
    const int c0 = blockIdx.x * 32, r0 = blockIdx.y * 32;
    const int tx = threadIdx.x, ty = threadIdx.y;
    #pragma unroll
    for (int j = 0; j < 4; j++)
        t[ty + j*8][tx] = src[(size_t)(r0 + ty + j*8) * C + c0 + tx];
    __syncthreads();
    #pragma unroll
    for (int j = 0; j < 4; j++) {
        const float v = t[tx][ty + j*8];
        __nv_bfloat16 h, l;
        split2(v, h, l);
        const size_t o = (size_t)(c0 + ty + j*8) * R + r0 + tx;
        dhi[o] = h; dlo[o] = l;
    }
}

// ---------------------------------------------------------------------------
// Masked softmax (keep t >= s), fp32 in -> bf16 hi/lo out, exp cached in regs
// ---------------------------------------------------------------------------
__global__ void __launch_bounds__(256) softmax_split(const float* __restrict__ sc,
                                                     __nv_bfloat16* __restrict__ whi,
                                                     __nv_bfloat16* __restrict__ wlo)
{
    const int s = blockIdx.x, b = blockIdx.y;
    const size_t base = ((size_t)b * SEQ + s) * SEQ;
    const float* row = sc + base;
    const int tid = threadIdx.x;
    __shared__ float red[256];

    float m = -1e30f;
    for (int t = s + tid; t < SEQ; t += 256) m = fmaxf(m, row[t]);
    red[tid] = m; __syncthreads();
    #pragma unroll
    for (int o = 128; o > 0; o >>= 1) {
        if (tid < o) red[tid] = fmaxf(red[tid], red[tid + o]);
        __syncthreads();
    }
    m = red[0]; __syncthreads();

    float ev[8];
    float sum = 0.f;
    {
        int j = 0;
        for (int t = s + tid; t < SEQ; t += 256, j++) {
            const float e = expf(row[t] - m);
            ev[j] = e;
            sum += e;
        }
    }
    red[tid] = sum; __syncthreads();
    #pragma unroll
    for (int o = 128; o > 0; o >>= 1) {
        if (tid < o) red[tid] += red[tid + o];
        __syncthreads();
    }
    const float inv = 1.f / red[0];

    for (int t = tid; t < s; t += 256) {
        whi[base + t] = __float2bfloat16(0.f);
        wlo[base + t] = __float2bfloat16(0.f);
    }
    {
        int j = 0;
        for (int t = s + tid; t < SEQ; t += 256, j++) {
            __nv_bfloat16 h, l;
            split2(ev[j] * inv, h, l);
            whi[base + t] = h;
            wlo[base + t] = l;
        }
    }
}

// ---------------------------------------------------------------------------
// Host
// ---------------------------------------------------------------------------
template <typename T>
static T* sym(const void* s) { void* p = nullptr; cudaGetSymbolAddress(&p, s); return (T*)p; }

static void launch_gemm(GP& p, int M, int N, int Z)
{
    dim3 g(N / 256, M / 128, Z);
    tgemm<<<g, 256, GEMM_SMEM>>>(p);
}

extern "C" void kernel_launch(void* const* d_in, const int* in_sizes, int n_in,
                              void* d_out, int out_size)
{
    const int*   x   = (const int*)  d_in[0];
    const float* emb = (const float*)d_in[1];
    const float* Wq  = (const float*)d_in[2];
    const float* bq  = (const float*)d_in[3];
    const float* Wk  = (const float*)d_in[4];
    const float* bk  = (const float*)d_in[5];
    const float* Wv  = (const float*)d_in[6];
    const float* bv  = (const float*)d_in[7];
    const float* W1  = (const float*)d_in[8];
    const float* b1  = (const float*)d_in[9];
    const float* W2  = (const float*)d_in[10];
    const float* b2  = (const float*)d_in[11];
    float* out = (float*)d_out;

    cudaFuncSetAttribute(tgemm, cudaFuncAttributeMaxDynamicSharedMemorySize, GEMM_SMEM);

    __nv_bfloat16* hhi = sym<__nv_bfloat16>(g_hhi);
    __nv_bfloat16* hlo = sym<__nv_bfloat16>(g_hlo);
    __nv_bfloat16* qhi = sym<__nv_bfloat16>(g_qhi);
    __nv_bfloat16* qlo = sym<__nv_bfloat16>(g_qlo);
    __nv_bfloat16* khi = sym<__nv_bfloat16>(g_khi);
    __nv_bfloat16* klo = sym<__nv_bfloat16>(g_klo);
    float*         v   = sym<float>(g_v);
    __nv_bfloat16* vthi= sym<__nv_bfloat16>(g_vthi);
    __nv_bfloat16* vtlo= sym<__nv_bfloat16>(g_vtlo);
    float*         sc  = sym<float>(g_sc);
    __nv_bfloat16* whi = sym<__nv_bfloat16>(g_whi);
    __nv_bfloat16* wlo = sym<__nv_bfloat16>(g_wlo);
    __nv_bfloat16* mhi = sym<__nv_bfloat16>(g_mhi);
    __nv_bfloat16* mlo = sym<__nv_bfloat16>(g_mlo);
    __nv_bfloat16* wqt = sym<__nv_bfloat16>(g_wqt);
    __nv_bfloat16* wkt = sym<__nv_bfloat16>(g_wkt);
    __nv_bfloat16* wvt = sym<__nv_bfloat16>(g_wvt);
    __nv_bfloat16* w1t = sym<__nv_bfloat16>(g_w1t);
    __nv_bfloat16* w2t = sym<__nv_bfloat16>(g_w2t);

    const size_t EE = (size_t)EDIM * EDIM;
    const size_t EM = (size_t)EDIM * MDIM;

    dim3 tb(32, 8);
    transpose_split<<<dim3(EDIM/32, EDIM/32, 1), tb>>>(Wq, wqt, wqt + EE, EDIM, EDIM, 0, 0);
    transpose_split<<<dim3(EDIM/32, EDIM/32, 1), tb>>>(Wk, wkt, wkt + EE, EDIM, EDIM, 0, 0);
    transpose_split<<<dim3(EDIM/32, EDIM/32, 1), tb>>>(Wv, wvt, wvt + EE, EDIM, EDIM, 0, 0);
    transpose_split<<<dim3(MDIM/32, EDIM/32, NLAY), tb>>>(W1, w1t, w1t + (size_t)NLAY*EM, EDIM, MDIM, EM, EM);
    transpose_split<<<dim3(EDIM/32, MDIM/32, NLAY), tb>>>(W2, w2t, w2t + (size_t)NLAY*EM, MDIM, EDIM, EM, EM);

    embed_split<<<NROWS, 256>>>(x, emb, hhi, hlo);

    GP p = {};
    p.Ahi = hhi; p.Alo = hlo; p.ldA = EDIM; p.ldB = EDIM; p.ldC = EDIM;
    p.K = EDIM; p.scale = 1.f; p.relu = 0; p.maskSkip = 0; p.triK = 0;
    p.szA = p.szB = p.szC = 0;

    p.Bhi = wqt; p.Blo = wqt + EE; p.bias = bq;
    p.outHi = qhi; p.outLo = qlo; p.outF = nullptr;
    launch_gemm(p, NROWS, EDIM, 1);

    p.Bhi = wkt; p.Blo = wkt + EE; p.bias = bk;
    p.outHi = khi; p.outLo = klo;
    launch_gemm(p, NROWS, EDIM, 1);

    p.Bhi = wvt; p.Blo = wvt + EE; p.bias = bv;
    p.outHi = nullptr; p.outLo = nullptr; p.outF = v;
    launch_gemm(p, NROWS, EDIM, 1);

    transpose_split<<<dim3(EDIM/32, SEQ/32, BATCH), tb>>>(v, vthi, vtlo, SEQ, EDIM,
                                                          (size_t)SEQ*EDIM, (size_t)EDIM*SEQ);

    // scores = scale * q k^T  (batched, masked-tile skip)
    p.Ahi = qhi; p.Alo = qlo; p.Bhi = khi; p.Blo = klo;
    p.ldA = EDIM; p.ldB = EDIM; p.ldC = SEQ; p.K = EDIM;
    p.szA = (size_t)SEQ * EDIM; p.szB = (size_t)SEQ * EDIM; p.szC = (size_t)SEQ * SEQ;
    p.bias = nullptr; p.outF = sc; p.outHi = nullptr; p.outLo = nullptr;
    p.scale = 1.f / 32.f; p.relu = 0; p.maskSkip = 1; p.triK = 0;
    launch_gemm(p, SEQ, SEQ, BATCH);

    softmax_split<<<dim3(SEQ, BATCH), 256>>>(sc, whi, wlo);

    // h = relu(w v)  (batched, triangular K skip)
    p.Ahi = whi; p.Alo = wlo; p.Bhi = vthi; p.Blo = vtlo;
    p.ldA = SEQ; p.ldB = SEQ; p.ldC = EDIM; p.K = SEQ;
    p.szA = (size_t)SEQ * SEQ; p.szB = (size_t)EDIM * SEQ; p.szC = (size_t)SEQ * EDIM;
    p.bias = nullptr; p.outF = nullptr; p.outHi = hhi; p.outLo = hlo;
    p.scale = 1.f; p.relu = 1; p.maskSkip = 0; p.triK = 1;
    launch_gemm(p, SEQ, EDIM, BATCH);

    // MLP stack
    __nv_bfloat16 *curHi = hhi, *curLo = hlo;
    __nv_bfloat16 *altHi = qhi, *altLo = qlo;
    for (int i = 0; i < NLAY; i++) {
        p.Ahi = curHi; p.Alo = curLo;
        p.Bhi = w1t + (size_t)i * EM; p.Blo = w1t + (size_t)(NLAY + i) * EM;
        p.ldA = EDIM; p.ldB = EDIM; p.ldC = MDIM; p.K = EDIM;
        p.szA = p.szB = p.szC = 0;
        p.bias = b1 + (size_t)i * MDIM;
        p.outHi = mhi; p.outLo = mlo; p.outF = nullptr;
        p.scale = 1.f; p.relu = 1; p.maskSkip = 0; p.triK = 0;
        launch_gemm(p, NROWS, MDIM, 1);

        p.Ahi = mhi; p.Alo = mlo;
        p.Bhi = w2t + (size_t)i * EM; p.Blo = w2t + (size_t)(NLAY + i) * EM;
        p.ldA = MDIM; p.ldB = MDIM; p.ldC = EDIM; p.K = MDIM;
        p.bias = b2 + (size_t)i * EDIM;
        if (i == NLAY - 1) {
            p.outHi = nullptr; p.outLo = nullptr; p.outF = out;
        } else {
            p.outHi = altHi; p.outLo = altLo; p.outF = nullptr;
        }
        launch_gemm(p, NROWS, EDIM, 1);

        __nv_bfloat16* t;
        t = curHi; curHi = altHi; altHi = t;
        t = curLo; curLo = altLo; altLo = t;
    }
}